// round 6
// baseline (speedup 1.0000x reference)
#include <cuda_runtime.h>
#include <cuda_fp16.h>
#include <cstdint>
#include <math_constants.h>

// Problem constants
#define CDIM 512
#define NHEAD 16
#define HD 32
#define LTOK 49
#define BNW 4096
#define MROWS (BNW * LTOK)            // 200704
#define NQKV (3 * CDIM)               // 1536
#define SLAB (LTOK * HD)              // 1568
#define WINSTRIDE (NHEAD * SLAB)      // 25088
#define PARTSTRIDE ((size_t)CDIM * MROWS)
#define KDIM 512
#define KITER (KDIM / 16)             // 32 iters of K=16
#define LP 52                          // padded token dim

// Scratch (device globals — no allocation)
__device__ float  g_qkvT[(size_t)NQKV * MROWS];     // qkv channel-major fp32
__device__ __half g_xhi[(size_t)MROWS * CDIM];      // x split hi/lo
__device__ __half g_xlo[(size_t)MROWS * CDIM];
__device__ __half g_ohi[(size_t)MROWS * CDIM];      // attn out split hi/lo
__device__ __half g_olo[(size_t)MROWS * CDIM];
__device__ __half g_whi1[(size_t)NQKV * KDIM];      // w_qkv^T hi/lo [N][K]
__device__ __half g_wlo1[(size_t)NQKV * KDIM];
__device__ __half g_whi2[(size_t)CDIM * KDIM];      // w_proj^T hi/lo
__device__ __half g_wlo2[(size_t)CDIM * KDIM];

// ---------------------------------------------------------------------------
// PTX helpers (sm_80-era ISA — tcgen05 unavailable at compute_103)
// ---------------------------------------------------------------------------
__device__ __forceinline__ uint32_t smem_u32(const void* p) {
    uint32_t a;
    asm("{ .reg .u64 t; cvta.to.shared.u64 t, %1; cvt.u32.u64 %0, t; }"
        : "=r"(a) : "l"(p));
    return a;
}
__device__ __forceinline__ void cp_async16(uint32_t smem, const void* g) {
    asm volatile("cp.async.cg.shared.global [%0], [%1], 16;"
                 :: "r"(smem), "l"(g) : "memory");
}
__device__ __forceinline__ void cp_commit() {
    asm volatile("cp.async.commit_group;" ::: "memory");
}
template <int N>
__device__ __forceinline__ void cp_wait() {
    asm volatile("cp.async.wait_group %0;" :: "n"(N) : "memory");
}
__device__ __forceinline__ void ldsm_x4(uint32_t& r0, uint32_t& r1,
                                        uint32_t& r2, uint32_t& r3,
                                        uint32_t addr) {
    asm volatile("ldmatrix.sync.aligned.m8n8.x4.shared.b16 {%0,%1,%2,%3}, [%4];"
                 : "=r"(r0), "=r"(r1), "=r"(r2), "=r"(r3) : "r"(addr));
}
__device__ __forceinline__ void mma_f16(float* d, const uint32_t* a,
                                        const uint32_t* b) {
    asm volatile(
        "mma.sync.aligned.m16n8k16.row.col.f32.f16.f16.f32 "
        "{%0,%1,%2,%3}, {%4,%5,%6,%7}, {%8,%9}, {%0,%1,%2,%3};"
        : "+f"(d[0]), "+f"(d[1]), "+f"(d[2]), "+f"(d[3])
        : "r"(a[0]), "r"(a[1]), "r"(a[2]), "r"(a[3]), "r"(b[0]), "r"(b[1]));
}

#define STAGE_BYTES 16384
#define NSTAGE 5
#define DYN_SMEM (NSTAGE * STAGE_BYTES)   // 81920; bounce needs 33280 <= this

__device__ __forceinline__ uint32_t sw16(int row, int c) {
    return (uint32_t)row * 32u + (uint32_t)((c ^ ((row >> 2) & 1)) << 4);
}

// ---------------------------------------------------------------------------
// x -> hi/lo fp16 split (elementwise)
// ---------------------------------------------------------------------------
__global__ __launch_bounds__(256) void split_x_kernel(const float* __restrict__ src) {
    size_t i = ((size_t)blockIdx.x * 256 + threadIdx.x) * 4;
    float4 v = *(const float4*)(src + i);
    __half h0 = __float2half_rn(v.x), h1 = __float2half_rn(v.y);
    __half h2 = __float2half_rn(v.z), h3 = __float2half_rn(v.w);
    __half l0 = __float2half_rn(v.x - __half2float(h0));
    __half l1 = __float2half_rn(v.y - __half2float(h1));
    __half l2 = __float2half_rn(v.z - __half2float(h2));
    __half l3 = __float2half_rn(v.w - __half2float(h3));
    __half2 hh[2] = {__halves2half2(h0, h1), __halves2half2(h2, h3)};
    __half2 ll[2] = {__halves2half2(l0, l1), __halves2half2(l2, l3)};
    *(uint2*)(g_xhi + i) = *(uint2*)hh;
    *(uint2*)(g_xlo + i) = *(uint2*)ll;
}

// ---------------------------------------------------------------------------
// Weight transpose + split: src[k*N + n] -> dst_{hi,lo}[n*K + k]
// ---------------------------------------------------------------------------
template <int SEL>
__global__ void wtrans_kernel(const float* __restrict__ src, int K, int N) {
    __half* dhi = (SEL == 1) ? g_whi1 : g_whi2;
    __half* dlo = (SEL == 1) ? g_wlo1 : g_wlo2;
    __shared__ float t[32][33];
    int n0 = blockIdx.x * 32, k0 = blockIdx.y * 32;
    int x = threadIdx.x, y = threadIdx.y;
    #pragma unroll
    for (int i = y; i < 32; i += 8)
        t[i][x] = src[(size_t)(k0 + i) * N + n0 + x];
    __syncthreads();
    #pragma unroll
    for (int i = y; i < 32; i += 8) {
        float v = t[x][i];
        __half h = __float2half_rn(v);
        __half l = __float2half_rn(v - __half2float(h));
        dhi[(size_t)(n0 + i) * K + k0 + x] = h;
        dlo[(size_t)(n0 + i) * K + k0 + x] = l;
    }
}

// ---------------------------------------------------------------------------
// fp16x3 mma.sync GEMM: 128x128 CTA tile, 4 warps (2x2) of 64x64 warp tiles,
// 128 threads, 5-stage cp.async pipeline, 96 MMAs per warp per barrier.
// MODE 1: scatter epilogue g_qkvT[col*MROWS+row]; MODE 2: row-major to C.
// ---------------------------------------------------------------------------
template <int MODE>
__global__ __launch_bounds__(128) void gemm_f16x3(
    const float* __restrict__ bias, float* __restrict__ C, int N)
{
    extern __shared__ char smem[];
    const __half* Ahi = (MODE == 1) ? g_xhi : g_ohi;
    const __half* Alo = (MODE == 1) ? g_xlo : g_olo;
    const __half* Bhi = (MODE == 1) ? g_whi1 : g_whi2;
    const __half* Blo = (MODE == 1) ? g_wlo1 : g_wlo2;

    const int tid = threadIdx.x;
    const int lane = tid & 31, wid = tid >> 5;
    const int warpM = wid & 1, warpN = wid >> 1;   // 2 x 2 warps, 64x64 tiles
    const int bm = blockIdx.y, bn = blockIdx.x;
    const uint32_t sbase = smem_u32(smem);

    // loader: 128 threads, per plane 256 chunks -> rows tid>>1 and +64, chunk tid&1
    const int grow = tid >> 1, gch = tid & 1;
    const uint32_t soff0 = sw16(grow, gch);
    const uint32_t soff1 = sw16(grow + 64, gch);
    const __half* gAhi = Ahi + (size_t)(bm * 128 + grow) * KDIM + gch * 8;
    const __half* gAlo = Alo + (size_t)(bm * 128 + grow) * KDIM + gch * 8;
    const __half* gBhi = Bhi + (size_t)(bn * 128 + grow) * KDIM + gch * 8;
    const __half* gBlo = Blo + (size_t)(bn * 128 + grow) * KDIM + gch * 8;
    const size_t rowskip = (size_t)64 * KDIM;

    float acc[4][8][4];
    #pragma unroll
    for (int i = 0; i < 4; i++)
        #pragma unroll
        for (int j = 0; j < 8; j++)
            #pragma unroll
            for (int q = 0; q < 4; q++) acc[i][j][q] = 0.f;

    // prologue: NSTAGE-1 stages in flight
    #pragma unroll
    for (int s = 0; s < NSTAGE - 1; s++) {
        uint32_t st = sbase + s * STAGE_BYTES;
        int k0 = s * 16;
        cp_async16(st + soff0,         gAhi + k0);
        cp_async16(st + soff1,         gAhi + rowskip + k0);
        cp_async16(st + 4096 + soff0,  gAlo + k0);
        cp_async16(st + 4096 + soff1,  gAlo + rowskip + k0);
        cp_async16(st + 8192 + soff0,  gBhi + k0);
        cp_async16(st + 8192 + soff1,  gBhi + rowskip + k0);
        cp_async16(st + 12288 + soff0, gBlo + k0);
        cp_async16(st + 12288 + soff1, gBlo + rowskip + k0);
        cp_commit();
    }

    const int lrow = lane & 15, lhalf = lane >> 4;
    uint32_t offA[4], offB[4];
    #pragma unroll
    for (int mt = 0; mt < 4; mt++)
        offA[mt] = sw16(warpM * 64 + mt * 16 + lrow, lhalf);
    #pragma unroll
    for (int nt2 = 0; nt2 < 4; nt2++)
        offB[nt2] = sw16(warpN * 64 + nt2 * 16 + lrow, lhalf);

    for (int it = 0; it < KITER; it++) {
        cp_wait<NSTAGE - 2>();
        __syncthreads();

        if (it + NSTAGE - 1 < KITER) {
            int s = (it + NSTAGE - 1) % NSTAGE;
            uint32_t st = sbase + s * STAGE_BYTES;
            int k0 = (it + NSTAGE - 1) * 16;
            cp_async16(st + soff0,         gAhi + k0);
            cp_async16(st + soff1,         gAhi + rowskip + k0);
            cp_async16(st + 4096 + soff0,  gAlo + k0);
            cp_async16(st + 4096 + soff1,  gAlo + rowskip + k0);
            cp_async16(st + 8192 + soff0,  gBhi + k0);
            cp_async16(st + 8192 + soff1,  gBhi + rowskip + k0);
            cp_async16(st + 12288 + soff0, gBlo + k0);
            cp_async16(st + 12288 + soff1, gBlo + rowskip + k0);
        }
        cp_commit();

        const uint32_t st = sbase + (it % NSTAGE) * STAGE_BYTES;

        uint32_t ah[4][4], al[4][4], bh[8][2], bl[8][2];
        #pragma unroll
        for (int mt = 0; mt < 4; mt++) {
            ldsm_x4(ah[mt][0], ah[mt][1], ah[mt][2], ah[mt][3], st + offA[mt]);
            ldsm_x4(al[mt][0], al[mt][1], al[mt][2], al[mt][3], st + 4096 + offA[mt]);
        }
        #pragma unroll
        for (int nt2 = 0; nt2 < 4; nt2++) {
            uint32_t r0, r1, r2, r3;
            ldsm_x4(r0, r1, r2, r3, st + 8192 + offB[nt2]);
            bh[nt2 * 2 + 0][0] = r0; bh[nt2 * 2 + 0][1] = r2;
            bh[nt2 * 2 + 1][0] = r1; bh[nt2 * 2 + 1][1] = r3;
            ldsm_x4(r0, r1, r2, r3, st + 12288 + offB[nt2]);
            bl[nt2 * 2 + 0][0] = r0; bl[nt2 * 2 + 0][1] = r2;
            bl[nt2 * 2 + 1][0] = r1; bl[nt2 * 2 + 1][1] = r3;
        }
        #pragma unroll
        for (int mt = 0; mt < 4; mt++)
            #pragma unroll
            for (int nt = 0; nt < 8; nt++) {
                mma_f16(acc[mt][nt], ah[mt], bh[nt]);
                mma_f16(acc[mt][nt], ah[mt], bl[nt]);
                mma_f16(acc[mt][nt], al[mt], bh[nt]);
            }
    }

    cp_wait<0>();
    __syncthreads();   // before smem reuse as bounce

    if (MODE == 2) {
        #pragma unroll
        for (int mt = 0; mt < 4; mt++) {
            #pragma unroll
            for (int nt = 0; nt < 8; nt++) {
                int m0 = bm * 128 + warpM * 64 + mt * 16 + (lane >> 2);
                int n0 = bn * 128 + warpN * 64 + nt * 8 + (lane & 3) * 2;
                float2 bv = *(const float2*)(bias + n0);
                float2 v0 = make_float2(acc[mt][nt][0] + bv.x, acc[mt][nt][1] + bv.y);
                float2 v1 = make_float2(acc[mt][nt][2] + bv.x, acc[mt][nt][3] + bv.y);
                *(float2*)(C + (size_t)m0 * N + n0) = v0;
                *(float2*)(C + (size_t)(m0 + 8) * N + n0) = v1;
            }
        }
    } else {
        // two 32-col passes through per-warp bounce [32 n][65]
        float* bounce = (float*)smem + wid * (32 * 65);
        #pragma unroll
        for (int pass = 0; pass < 2; pass++) {
            #pragma unroll
            for (int mt = 0; mt < 4; mt++) {
                #pragma unroll
                for (int ntl = 0; ntl < 4; ntl++) {
                    int nt = pass * 4 + ntl;
                    int nl = ntl * 8 + (lane & 3) * 2;
                    int ml = mt * 16 + (lane >> 2);
                    bounce[nl * 65 + ml]            = acc[mt][nt][0];
                    bounce[(nl + 1) * 65 + ml]      = acc[mt][nt][1];
                    bounce[nl * 65 + ml + 8]        = acc[mt][nt][2];
                    bounce[(nl + 1) * 65 + ml + 8]  = acc[mt][nt][3];
                }
            }
            __syncwarp();
            int col = bn * 128 + warpN * 64 + pass * 32 + lane;
            float bv = bias[col];
            float* dst = g_qkvT + (size_t)col * MROWS + bm * 128 + warpM * 64;
            const float* src = bounce + lane * 65;
            #pragma unroll
            for (int q = 0; q < 16; q++) {
                float4 v;
                v.x = src[q * 4 + 0] + bv;
                v.y = src[q * 4 + 1] + bv;
                v.z = src[q * 4 + 2] + bv;
                v.w = src[q * 4 + 3] + bv;
                ((float4*)dst)[q] = v;
            }
            __syncwarp();
        }
    }
}

// ---------------------------------------------------------------------------
// Attention (register-tiled, unchanged from R5 — passing, ~0.9ms)
// ---------------------------------------------------------------------------
__global__ __launch_bounds__(256) void attn_kernel(
    const float* __restrict__ mask,
    const float* __restrict__ bias_table,
    const int*   __restrict__ index_table)
{
    __shared__ float sQT[HD * LP];
    __shared__ float sKT[HD * LP];
    __shared__ float sV[LTOK * HD];
    __shared__ float sS[LP * LP];

    int tid = threadIdx.x;
    int b2 = blockIdx.x >> 4;
    int h  = blockIdx.x & 15;

    size_t base = (size_t)b2 * WINSTRIDE + (size_t)h * SLAB;
    const float* Qg = g_qkvT + base;
    const float* Kg = g_qkvT + PARTSTRIDE + base;
    const float* Vg = g_qkvT + 2 * PARTSTRIDE + base;

    for (int t = tid; t < SLAB / 4; t += 256) {
        float4 qv = ((const float4*)Qg)[t];
        float4 kv = ((const float4*)Kg)[t];
        ((float4*)sV)[t] = ((const float4*)Vg)[t];
        int j  = t * 4;
        int l2 = j >> 5;
        int d  = j & 31;
        sQT[(d + 0) * LP + l2] = qv.x;
        sQT[(d + 1) * LP + l2] = qv.y;
        sQT[(d + 2) * LP + l2] = qv.z;
        sQT[(d + 3) * LP + l2] = qv.w;
        sKT[(d + 0) * LP + l2] = kv.x;
        sKT[(d + 1) * LP + l2] = kv.y;
        sKT[(d + 2) * LP + l2] = kv.z;
        sKT[(d + 3) * LP + l2] = kv.w;
    }
    __syncthreads();

    const float* mrow = mask + (size_t)(b2 & 63) * (LTOK * LTOK);
    if (tid < 169) {
        int lt = tid / 13, mt = tid - lt * 13;
        int l0 = lt * 4, m0 = mt * 4;
        float acc[4][4];
        #pragma unroll
        for (int i = 0; i < 4; i++)
            #pragma unroll
            for (int j = 0; j < 4; j++) acc[i][j] = 0.f;
        #pragma unroll
        for (int d = 0; d < HD; d++) {
            float4 q = *(const float4*)&sQT[d * LP + l0];
            float4 k = *(const float4*)&sKT[d * LP + m0];
            float qa[4] = {q.x, q.y, q.z, q.w};
            float ka[4] = {k.x, k.y, k.z, k.w};
            #pragma unroll
            for (int i = 0; i < 4; i++)
                #pragma unroll
                for (int j = 0; j < 4; j++)
                    acc[i][j] = fmaf(qa[i], ka[j], acc[i][j]);
        }
        #pragma unroll
        for (int i = 0; i < 4; i++) {
            int l = l0 + i;
            if (l < LTOK) {
                #pragma unroll
                for (int j = 0; j < 4; j++) {
                    int m = m0 + j;
                    if (m < LTOK) {
                        int o = l * LTOK + m;
                        sS[l * LP + m] = acc[i][j]
                            + bias_table[index_table[o] * NHEAD + h] + mrow[o];
                    }
                }
            }
        }
    }
    __syncthreads();

    int warp = tid >> 5, lane = tid & 31;
    for (int row = warp; row < LTOK; row += 8) {
        float* s = sS + row * LP;
        float e0 = s[lane];
        float e1 = (lane + 32 < LTOK) ? s[lane + 32] : -CUDART_INF_F;
        float mx = fmaxf(e0, e1);
        #pragma unroll
        for (int off = 16; off; off >>= 1)
            mx = fmaxf(mx, __shfl_xor_sync(0xffffffffu, mx, off));
        float p0 = __expf(e0 - mx);
        float p1 = (lane + 32 < LTOK) ? __expf(e1 - mx) : 0.f;
        float sum = p0 + p1;
        #pragma unroll
        for (int off = 16; off; off >>= 1)
            sum += __shfl_xor_sync(0xffffffffu, sum, off);
        float inv = 1.f / sum;
        s[lane] = p0 * inv;
        if (lane + 32 < LTOK) s[lane + 32] = p1 * inv;
    }
    __syncthreads();

    if (tid < 104) {
        int dt = tid & 7, lt = tid >> 3;
        int l0 = lt * 4, d0 = dt * 4;
        float acc[4][4];
        #pragma unroll
        for (int i = 0; i < 4; i++)
            #pragma unroll
            for (int j = 0; j < 4; j++) acc[i][j] = 0.f;
        for (int m = 0; m < LTOK; m++) {
            float4 v = *(const float4*)&sV[m * HD + d0];
            float va[4] = {v.x, v.y, v.z, v.w};
            float p0 = sS[(l0 + 0) * LP + m];
            float p1 = sS[(l0 + 1) * LP + m];
            float p2 = sS[(l0 + 2) * LP + m];
            float p3 = sS[(l0 + 3) * LP + m];
            #pragma unroll
            for (int j = 0; j < 4; j++) {
                acc[0][j] = fmaf(p0, va[j], acc[0][j]);
                acc[1][j] = fmaf(p1, va[j], acc[1][j]);
                acc[2][j] = fmaf(p2, va[j], acc[2][j]);
                acc[3][j] = fmaf(p3, va[j], acc[3][j]);
            }
        }
        #pragma unroll
        for (int i = 0; i < 4; i++) {
            int l = l0 + i;
            if (l < LTOK) {
                size_t oidx = ((size_t)b2 * LTOK + l) * CDIM + h * HD + d0;
                __half hv[4], lv[4];
                #pragma unroll
                for (int j = 0; j < 4; j++) {
                    hv[j] = __float2half_rn(acc[i][j]);
                    lv[j] = __float2half_rn(acc[i][j] - __half2float(hv[j]));
                }
                *(uint2*)(g_ohi + oidx) = *(uint2*)hv;
                *(uint2*)(g_olo + oidx) = *(uint2*)lv;
            }
        }
    }
}

// ---------------------------------------------------------------------------
extern "C" void kernel_launch(void* const* d_in, const int* in_sizes, int n_in,
                              void* d_out, int out_size)
{
    const float* x           = (const float*)d_in[0];
    const float* mask        = (const float*)d_in[1];
    const float* w_qkv       = (const float*)d_in[2];
    const float* b_qkv       = (const float*)d_in[3];
    const float* w_proj      = (const float*)d_in[4];
    const float* b_proj      = (const float*)d_in[5];
    const float* bias_table  = (const float*)d_in[6];
    const int*   index_table = (const int*)d_in[7];
    float* out = (float*)d_out;

    cudaFuncSetAttribute(gemm_f16x3<1>, cudaFuncAttributeMaxDynamicSharedMemorySize, DYN_SMEM);
    cudaFuncSetAttribute(gemm_f16x3<2>, cudaFuncAttributeMaxDynamicSharedMemorySize, DYN_SMEM);

    // 0) weight transpose+split and x split
    wtrans_kernel<1><<<dim3(NQKV / 32, KDIM / 32), dim3(32, 8)>>>(w_qkv, KDIM, NQKV);
    wtrans_kernel<2><<<dim3(CDIM / 32, KDIM / 32), dim3(32, 8)>>>(w_proj, KDIM, CDIM);
    split_x_kernel<<<((size_t)MROWS * CDIM) / 4 / 256, 256>>>(x);

    // 1) QKV GEMM (fp16x3) with channel-major scatter epilogue
    gemm_f16x3<1><<<dim3(NQKV / 128, MROWS / 128), 128, DYN_SMEM>>>(b_qkv, nullptr, NQKV);

    // 2) fused window attention (register-tiled)
    attn_kernel<<<BNW * NHEAD, 256>>>(mask, bias_table, index_table);

    // 3) projection GEMM (fp16x3)
    gemm_f16x3<2><<<dim3(CDIM / 128, MROWS / 128), 128, DYN_SMEM>>>(b_proj, out, CDIM);
}

// round 7
// speedup vs baseline: 1.0274x; 1.0274x over previous
#include <cuda_runtime.h>
#include <cuda_fp16.h>
#include <cstdint>
#include <math_constants.h>

// Problem constants
#define CDIM 512
#define NHEAD 16
#define HD 32
#define LTOK 49
#define BNW 4096
#define MROWS (BNW * LTOK)            // 200704
#define NQKV (3 * CDIM)               // 1536
#define SLAB (LTOK * HD)              // 1568
#define WINSTRIDE (NHEAD * SLAB)      // 25088
#define PARTSTRIDE ((size_t)CDIM * MROWS)
#define KDIM 512
#define KITER (KDIM / 16)             // 32 iters of K=16
#define LP 52                          // padded token dim
#define LO_SCALE 1024.0f               // lo-plane scaling (exact pow2)
#define LO_UNSCALE 0.0009765625f       // 2^-10

// Scratch (device globals — no allocation)
__device__ float  g_qkvT[(size_t)NQKV * MROWS];     // qkv channel-major fp32
__device__ __half g_xhi[(size_t)MROWS * CDIM];      // x split hi/lo (lo *= 1024)
__device__ __half g_xlo[(size_t)MROWS * CDIM];
__device__ __half g_ohi[(size_t)MROWS * CDIM];      // attn out split hi/lo
__device__ __half g_olo[(size_t)MROWS * CDIM];
__device__ __half g_whi1[(size_t)NQKV * KDIM];      // w_qkv^T hi/lo [N][K]
__device__ __half g_wlo1[(size_t)NQKV * KDIM];
__device__ __half g_whi2[(size_t)CDIM * KDIM];      // w_proj^T hi/lo
__device__ __half g_wlo2[(size_t)CDIM * KDIM];

// ---------------------------------------------------------------------------
// PTX helpers (sm_80-era ISA — tcgen05 unavailable at compute_103)
// ---------------------------------------------------------------------------
__device__ __forceinline__ uint32_t smem_u32(const void* p) {
    uint32_t a;
    asm("{ .reg .u64 t; cvta.to.shared.u64 t, %1; cvt.u32.u64 %0, t; }"
        : "=r"(a) : "l"(p));
    return a;
}
__device__ __forceinline__ void cp_async16(uint32_t smem, const void* g) {
    asm volatile("cp.async.cg.shared.global [%0], [%1], 16;"
                 :: "r"(smem), "l"(g) : "memory");
}
__device__ __forceinline__ void cp_commit() {
    asm volatile("cp.async.commit_group;" ::: "memory");
}
template <int N>
__device__ __forceinline__ void cp_wait() {
    asm volatile("cp.async.wait_group %0;" :: "n"(N) : "memory");
}
__device__ __forceinline__ void ldsm_x4(uint32_t& r0, uint32_t& r1,
                                        uint32_t& r2, uint32_t& r3,
                                        uint32_t addr) {
    asm volatile("ldmatrix.sync.aligned.m8n8.x4.shared.b16 {%0,%1,%2,%3}, [%4];"
                 : "=r"(r0), "=r"(r1), "=r"(r2), "=r"(r3) : "r"(addr));
}
// fp32-accumulate HMMA (full rate for main term)
__device__ __forceinline__ void mma_f16(float* d, const uint32_t* a,
                                        const uint32_t* b) {
    asm volatile(
        "mma.sync.aligned.m16n8k16.row.col.f32.f16.f16.f32 "
        "{%0,%1,%2,%3}, {%4,%5,%6,%7}, {%8,%9}, {%0,%1,%2,%3};"
        : "+f"(d[0]), "+f"(d[1]), "+f"(d[2]), "+f"(d[3])
        : "r"(a[0]), "r"(a[1]), "r"(a[2]), "r"(a[3]), "r"(b[0]), "r"(b[1]));
}
// fp16-accumulate HMMA (2x rate) for correction terms
__device__ __forceinline__ void mma_f16acc(uint32_t* d, const uint32_t* a,
                                           const uint32_t* b) {
    asm volatile(
        "mma.sync.aligned.m16n8k16.row.col.f16.f16.f16.f16 "
        "{%0,%1}, {%2,%3,%4,%5}, {%6,%7}, {%0,%1};"
        : "+r"(d[0]), "+r"(d[1])
        : "r"(a[0]), "r"(a[1]), "r"(a[2]), "r"(a[3]), "r"(b[0]), "r"(b[1]));
}

#define STAGE_BYTES 16384
#define NSTAGE 5
#define DYN_SMEM (NSTAGE * STAGE_BYTES)   // 81920; bounce needs 33280 <= this

__device__ __forceinline__ uint32_t sw16(int row, int c) {
    return (uint32_t)row * 32u + (uint32_t)((c ^ ((row >> 2) & 1)) << 4);
}

// ---------------------------------------------------------------------------
// x -> hi/lo fp16 split (lo scaled by 1024)
// ---------------------------------------------------------------------------
__global__ __launch_bounds__(256) void split_x_kernel(const float* __restrict__ src) {
    size_t i = ((size_t)blockIdx.x * 256 + threadIdx.x) * 4;
    float4 v = *(const float4*)(src + i);
    __half h0 = __float2half_rn(v.x), h1 = __float2half_rn(v.y);
    __half h2 = __float2half_rn(v.z), h3 = __float2half_rn(v.w);
    __half l0 = __float2half_rn((v.x - __half2float(h0)) * LO_SCALE);
    __half l1 = __float2half_rn((v.y - __half2float(h1)) * LO_SCALE);
    __half l2 = __float2half_rn((v.z - __half2float(h2)) * LO_SCALE);
    __half l3 = __float2half_rn((v.w - __half2float(h3)) * LO_SCALE);
    __half2 hh[2] = {__halves2half2(h0, h1), __halves2half2(h2, h3)};
    __half2 ll[2] = {__halves2half2(l0, l1), __halves2half2(l2, l3)};
    *(uint2*)(g_xhi + i) = *(uint2*)hh;
    *(uint2*)(g_xlo + i) = *(uint2*)ll;
}

// ---------------------------------------------------------------------------
// Weight transpose + split (lo scaled by 1024)
// ---------------------------------------------------------------------------
template <int SEL>
__global__ void wtrans_kernel(const float* __restrict__ src, int K, int N) {
    __half* dhi = (SEL == 1) ? g_whi1 : g_whi2;
    __half* dlo = (SEL == 1) ? g_wlo1 : g_wlo2;
    __shared__ float t[32][33];
    int n0 = blockIdx.x * 32, k0 = blockIdx.y * 32;
    int x = threadIdx.x, y = threadIdx.y;
    #pragma unroll
    for (int i = y; i < 32; i += 8)
        t[i][x] = src[(size_t)(k0 + i) * N + n0 + x];
    __syncthreads();
    #pragma unroll
    for (int i = y; i < 32; i += 8) {
        float v = t[x][i];
        __half h = __float2half_rn(v);
        __half l = __float2half_rn((v - __half2float(h)) * LO_SCALE);
        dhi[(size_t)(n0 + i) * K + k0 + x] = h;
        dlo[(size_t)(n0 + i) * K + k0 + x] = l;
    }
}

// ---------------------------------------------------------------------------
// fp16 split GEMM: main term fp32-acc HMMA, correction terms fp16-acc HMMA.
// 128x128 CTA tile, 4 warps (2x2) of 64x64, 128 threads, 5-stage cp.async.
// MODE 1: scatter epilogue g_qkvT[col*MROWS+row]; MODE 2: row-major to C.
// ---------------------------------------------------------------------------
template <int MODE>
__global__ __launch_bounds__(128) void gemm_f16x3(
    const float* __restrict__ bias, float* __restrict__ C, int N)
{
    extern __shared__ char smem[];
    const __half* Ahi = (MODE == 1) ? g_xhi : g_ohi;
    const __half* Alo = (MODE == 1) ? g_xlo : g_olo;
    const __half* Bhi = (MODE == 1) ? g_whi1 : g_whi2;
    const __half* Blo = (MODE == 1) ? g_wlo1 : g_wlo2;

    const int tid = threadIdx.x;
    const int lane = tid & 31, wid = tid >> 5;
    const int warpM = wid & 1, warpN = wid >> 1;   // 2 x 2 warps, 64x64 tiles
    const int bm = blockIdx.y, bn = blockIdx.x;
    const uint32_t sbase = smem_u32(smem);

    const int grow = tid >> 1, gch = tid & 1;
    const uint32_t soff0 = sw16(grow, gch);
    const uint32_t soff1 = sw16(grow + 64, gch);
    const __half* gAhi = Ahi + (size_t)(bm * 128 + grow) * KDIM + gch * 8;
    const __half* gAlo = Alo + (size_t)(bm * 128 + grow) * KDIM + gch * 8;
    const __half* gBhi = Bhi + (size_t)(bn * 128 + grow) * KDIM + gch * 8;
    const __half* gBlo = Blo + (size_t)(bn * 128 + grow) * KDIM + gch * 8;
    const size_t rowskip = (size_t)64 * KDIM;

    float acc[4][8][4];
    uint32_t accx[4][8][2];            // fp16 accumulators for cross terms
    #pragma unroll
    for (int i = 0; i < 4; i++)
        #pragma unroll
        for (int j = 0; j < 8; j++) {
            #pragma unroll
            for (int q = 0; q < 4; q++) acc[i][j][q] = 0.f;
            accx[i][j][0] = 0u; accx[i][j][1] = 0u;
        }

    #pragma unroll
    for (int s = 0; s < NSTAGE - 1; s++) {
        uint32_t st = sbase + s * STAGE_BYTES;
        int k0 = s * 16;
        cp_async16(st + soff0,         gAhi + k0);
        cp_async16(st + soff1,         gAhi + rowskip + k0);
        cp_async16(st + 4096 + soff0,  gAlo + k0);
        cp_async16(st + 4096 + soff1,  gAlo + rowskip + k0);
        cp_async16(st + 8192 + soff0,  gBhi + k0);
        cp_async16(st + 8192 + soff1,  gBhi + rowskip + k0);
        cp_async16(st + 12288 + soff0, gBlo + k0);
        cp_async16(st + 12288 + soff1, gBlo + rowskip + k0);
        cp_commit();
    }

    const int lrow = lane & 15, lhalf = lane >> 4;
    uint32_t offA[4], offB[4];
    #pragma unroll
    for (int mt = 0; mt < 4; mt++)
        offA[mt] = sw16(warpM * 64 + mt * 16 + lrow, lhalf);
    #pragma unroll
    for (int nt2 = 0; nt2 < 4; nt2++)
        offB[nt2] = sw16(warpN * 64 + nt2 * 16 + lrow, lhalf);

    for (int it = 0; it < KITER; it++) {
        cp_wait<NSTAGE - 2>();
        __syncthreads();

        if (it + NSTAGE - 1 < KITER) {
            int s = (it + NSTAGE - 1) % NSTAGE;
            uint32_t st = sbase + s * STAGE_BYTES;
            int k0 = (it + NSTAGE - 1) * 16;
            cp_async16(st + soff0,         gAhi + k0);
            cp_async16(st + soff1,         gAhi + rowskip + k0);
            cp_async16(st + 4096 + soff0,  gAlo + k0);
            cp_async16(st + 4096 + soff1,  gAlo + rowskip + k0);
            cp_async16(st + 8192 + soff0,  gBhi + k0);
            cp_async16(st + 8192 + soff1,  gBhi + rowskip + k0);
            cp_async16(st + 12288 + soff0, gBlo + k0);
            cp_async16(st + 12288 + soff1, gBlo + rowskip + k0);
        }
        cp_commit();

        const uint32_t st = sbase + (it % NSTAGE) * STAGE_BYTES;

        uint32_t ah[4][4], al[4][4], bh[8][2], bl[8][2];
        #pragma unroll
        for (int mt = 0; mt < 4; mt++) {
            ldsm_x4(ah[mt][0], ah[mt][1], ah[mt][2], ah[mt][3], st + offA[mt]);
            ldsm_x4(al[mt][0], al[mt][1], al[mt][2], al[mt][3], st + 4096 + offA[mt]);
        }
        #pragma unroll
        for (int nt2 = 0; nt2 < 4; nt2++) {
            uint32_t r0, r1, r2, r3;
            ldsm_x4(r0, r1, r2, r3, st + 8192 + offB[nt2]);
            bh[nt2 * 2 + 0][0] = r0; bh[nt2 * 2 + 0][1] = r2;
            bh[nt2 * 2 + 1][0] = r1; bh[nt2 * 2 + 1][1] = r3;
            ldsm_x4(r0, r1, r2, r3, st + 12288 + offB[nt2]);
            bl[nt2 * 2 + 0][0] = r0; bl[nt2 * 2 + 0][1] = r2;
            bl[nt2 * 2 + 1][0] = r1; bl[nt2 * 2 + 1][1] = r3;
        }
        #pragma unroll
        for (int mt = 0; mt < 4; mt++)
            #pragma unroll
            for (int nt = 0; nt < 8; nt++) {
                mma_f16(acc[mt][nt], ah[mt], bh[nt]);          // fp32-acc
                mma_f16acc(accx[mt][nt], ah[mt], bl[nt]);      // fp16-acc 2x
                mma_f16acc(accx[mt][nt], al[mt], bh[nt]);      // fp16-acc 2x
            }
    }

    // merge fp16 cross-sums (scaled by 1024) into fp32 accumulators
    #pragma unroll
    for (int mt = 0; mt < 4; mt++)
        #pragma unroll
        for (int nt = 0; nt < 8; nt++) {
            __half2 p01 = *reinterpret_cast<__half2*>(&accx[mt][nt][0]);
            __half2 p23 = *reinterpret_cast<__half2*>(&accx[mt][nt][1]);
            float2 f01 = __half22float2(p01);
            float2 f23 = __half22float2(p23);
            acc[mt][nt][0] += f01.x * LO_UNSCALE;
            acc[mt][nt][1] += f01.y * LO_UNSCALE;
            acc[mt][nt][2] += f23.x * LO_UNSCALE;
            acc[mt][nt][3] += f23.y * LO_UNSCALE;
        }

    cp_wait<0>();
    __syncthreads();   // before smem reuse as bounce

    if (MODE == 2) {
        #pragma unroll
        for (int mt = 0; mt < 4; mt++) {
            #pragma unroll
            for (int nt = 0; nt < 8; nt++) {
                int m0 = bm * 128 + warpM * 64 + mt * 16 + (lane >> 2);
                int n0 = bn * 128 + warpN * 64 + nt * 8 + (lane & 3) * 2;
                float2 bv = *(const float2*)(bias + n0);
                float2 v0 = make_float2(acc[mt][nt][0] + bv.x, acc[mt][nt][1] + bv.y);
                float2 v1 = make_float2(acc[mt][nt][2] + bv.x, acc[mt][nt][3] + bv.y);
                *(float2*)(C + (size_t)m0 * N + n0) = v0;
                *(float2*)(C + (size_t)(m0 + 8) * N + n0) = v1;
            }
        }
    } else {
        float* bounce = (float*)smem + wid * (32 * 65);
        #pragma unroll
        for (int pass = 0; pass < 2; pass++) {
            #pragma unroll
            for (int mt = 0; mt < 4; mt++) {
                #pragma unroll
                for (int ntl = 0; ntl < 4; ntl++) {
                    int nt = pass * 4 + ntl;
                    int nl = ntl * 8 + (lane & 3) * 2;
                    int ml = mt * 16 + (lane >> 2);
                    bounce[nl * 65 + ml]            = acc[mt][nt][0];
                    bounce[(nl + 1) * 65 + ml]      = acc[mt][nt][1];
                    bounce[nl * 65 + ml + 8]        = acc[mt][nt][2];
                    bounce[(nl + 1) * 65 + ml + 8]  = acc[mt][nt][3];
                }
            }
            __syncwarp();
            int col = bn * 128 + warpN * 64 + pass * 32 + lane;
            float bv = bias[col];
            float* dst = g_qkvT + (size_t)col * MROWS + bm * 128 + warpM * 64;
            const float* src = bounce + lane * 65;
            #pragma unroll
            for (int q = 0; q < 16; q++) {
                float4 v;
                v.x = src[q * 4 + 0] + bv;
                v.y = src[q * 4 + 1] + bv;
                v.z = src[q * 4 + 2] + bv;
                v.w = src[q * 4 + 3] + bv;
                ((float4*)dst)[q] = v;
            }
            __syncwarp();
        }
    }
}

// ---------------------------------------------------------------------------
// Attention (register-tiled; lo output scaled by 1024)
// ---------------------------------------------------------------------------
__global__ __launch_bounds__(256) void attn_kernel(
    const float* __restrict__ mask,
    const float* __restrict__ bias_table,
    const int*   __restrict__ index_table)
{
    __shared__ float sQT[HD * LP];
    __shared__ float sKT[HD * LP];
    __shared__ float sV[LTOK * HD];
    __shared__ float sS[LP * LP];

    int tid = threadIdx.x;
    int b2 = blockIdx.x >> 4;
    int h  = blockIdx.x & 15;

    size_t base = (size_t)b2 * WINSTRIDE + (size_t)h * SLAB;
    const float* Qg = g_qkvT + base;
    const float* Kg = g_qkvT + PARTSTRIDE + base;
    const float* Vg = g_qkvT + 2 * PARTSTRIDE + base;

    for (int t = tid; t < SLAB / 4; t += 256) {
        float4 qv = ((const float4*)Qg)[t];
        float4 kv = ((const float4*)Kg)[t];
        ((float4*)sV)[t] = ((const float4*)Vg)[t];
        int j  = t * 4;
        int l2 = j >> 5;
        int d  = j & 31;
        sQT[(d + 0) * LP + l2] = qv.x;
        sQT[(d + 1) * LP + l2] = qv.y;
        sQT[(d + 2) * LP + l2] = qv.z;
        sQT[(d + 3) * LP + l2] = qv.w;
        sKT[(d + 0) * LP + l2] = kv.x;
        sKT[(d + 1) * LP + l2] = kv.y;
        sKT[(d + 2) * LP + l2] = kv.z;
        sKT[(d + 3) * LP + l2] = kv.w;
    }
    __syncthreads();

    const float* mrow = mask + (size_t)(b2 & 63) * (LTOK * LTOK);
    if (tid < 169) {
        int lt = tid / 13, mt = tid - lt * 13;
        int l0 = lt * 4, m0 = mt * 4;
        float acc[4][4];
        #pragma unroll
        for (int i = 0; i < 4; i++)
            #pragma unroll
            for (int j = 0; j < 4; j++) acc[i][j] = 0.f;
        #pragma unroll
        for (int d = 0; d < HD; d++) {
            float4 q = *(const float4*)&sQT[d * LP + l0];
            float4 k = *(const float4*)&sKT[d * LP + m0];
            float qa[4] = {q.x, q.y, q.z, q.w};
            float ka[4] = {k.x, k.y, k.z, k.w};
            #pragma unroll
            for (int i = 0; i < 4; i++)
                #pragma unroll
                for (int j = 0; j < 4; j++)
                    acc[i][j] = fmaf(qa[i], ka[j], acc[i][j]);
        }
        #pragma unroll
        for (int i = 0; i < 4; i++) {
            int l = l0 + i;
            if (l < LTOK) {
                #pragma unroll
                for (int j = 0; j < 4; j++) {
                    int m = m0 + j;
                    if (m < LTOK) {
                        int o = l * LTOK + m;
                        sS[l * LP + m] = acc[i][j]
                            + bias_table[index_table[o] * NHEAD + h] + mrow[o];
                    }
                }
            }
        }
    }
    __syncthreads();

    int warp = tid >> 5, lane = tid & 31;
    for (int row = warp; row < LTOK; row += 8) {
        float* s = sS + row * LP;
        float e0 = s[lane];
        float e1 = (lane + 32 < LTOK) ? s[lane + 32] : -CUDART_INF_F;
        float mx = fmaxf(e0, e1);
        #pragma unroll
        for (int off = 16; off; off >>= 1)
            mx = fmaxf(mx, __shfl_xor_sync(0xffffffffu, mx, off));
        float p0 = __expf(e0 - mx);
        float p1 = (lane + 32 < LTOK) ? __expf(e1 - mx) : 0.f;
        float sum = p0 + p1;
        #pragma unroll
        for (int off = 16; off; off >>= 1)
            sum += __shfl_xor_sync(0xffffffffu, sum, off);
        float inv = 1.f / sum;
        s[lane] = p0 * inv;
        if (lane + 32 < LTOK) s[lane + 32] = p1 * inv;
    }
    __syncthreads();

    if (tid < 104) {
        int dt = tid & 7, lt = tid >> 3;
        int l0 = lt * 4, d0 = dt * 4;
        float acc[4][4];
        #pragma unroll
        for (int i = 0; i < 4; i++)
            #pragma unroll
            for (int j = 0; j < 4; j++) acc[i][j] = 0.f;
        for (int m = 0; m < LTOK; m++) {
            float4 v = *(const float4*)&sV[m * HD + d0];
            float va[4] = {v.x, v.y, v.z, v.w};
            float p0 = sS[(l0 + 0) * LP + m];
            float p1 = sS[(l0 + 1) * LP + m];
            float p2 = sS[(l0 + 2) * LP + m];
            float p3 = sS[(l0 + 3) * LP + m];
            #pragma unroll
            for (int j = 0; j < 4; j++) {
                acc[0][j] = fmaf(p0, va[j], acc[0][j]);
                acc[1][j] = fmaf(p1, va[j], acc[1][j]);
                acc[2][j] = fmaf(p2, va[j], acc[2][j]);
                acc[3][j] = fmaf(p3, va[j], acc[3][j]);
            }
        }
        #pragma unroll
        for (int i = 0; i < 4; i++) {
            int l = l0 + i;
            if (l < LTOK) {
                size_t oidx = ((size_t)b2 * LTOK + l) * CDIM + h * HD + d0;
                __half hv[4], lv[4];
                #pragma unroll
                for (int j = 0; j < 4; j++) {
                    hv[j] = __float2half_rn(acc[i][j]);
                    lv[j] = __float2half_rn(
                        (acc[i][j] - __half2float(hv[j])) * LO_SCALE);
                }
                *(uint2*)(g_ohi + oidx) = *(uint2*)hv;
                *(uint2*)(g_olo + oidx) = *(uint2*)lv;
            }
        }
    }
}

// ---------------------------------------------------------------------------
extern "C" void kernel_launch(void* const* d_in, const int* in_sizes, int n_in,
                              void* d_out, int out_size)
{
    const float* x           = (const float*)d_in[0];
    const float* mask        = (const float*)d_in[1];
    const float* w_qkv       = (const float*)d_in[2];
    const float* b_qkv       = (const float*)d_in[3];
    const float* w_proj      = (const float*)d_in[4];
    const float* b_proj      = (const float*)d_in[5];
    const float* bias_table  = (const float*)d_in[6];
    const int*   index_table = (const int*)d_in[7];
    float* out = (float*)d_out;

    cudaFuncSetAttribute(gemm_f16x3<1>, cudaFuncAttributeMaxDynamicSharedMemorySize, DYN_SMEM);
    cudaFuncSetAttribute(gemm_f16x3<2>, cudaFuncAttributeMaxDynamicSharedMemorySize, DYN_SMEM);

    // 0) weight transpose+split and x split
    wtrans_kernel<1><<<dim3(NQKV / 32, KDIM / 32), dim3(32, 8)>>>(w_qkv, KDIM, NQKV);
    wtrans_kernel<2><<<dim3(CDIM / 32, KDIM / 32), dim3(32, 8)>>>(w_proj, KDIM, CDIM);
    split_x_kernel<<<((size_t)MROWS * CDIM) / 4 / 256, 256>>>(x);

    // 1) QKV GEMM with channel-major scatter epilogue
    gemm_f16x3<1><<<dim3(NQKV / 128, MROWS / 128), 128, DYN_SMEM>>>(b_qkv, nullptr, NQKV);

    // 2) fused window attention (register-tiled)
    attn_kernel<<<BNW * NHEAD, 256>>>(mask, bias_table, index_table);

    // 3) projection GEMM
    gemm_f16x3<2><<<dim3(CDIM / 128, MROWS / 128), 128, DYN_SMEM>>>(b_proj, out, CDIM);
}

// round 8
// speedup vs baseline: 1.2204x; 1.1879x over previous
#include <cuda_runtime.h>
#include <cuda_fp16.h>
#include <cstdint>
#include <math_constants.h>

// Problem constants
#define CDIM 512
#define NHEAD 16
#define HD 32
#define LTOK 49
#define BNW 4096
#define MROWS (BNW * LTOK)            // 200704
#define NQKV (3 * CDIM)               // 1536
#define SLAB (LTOK * HD)              // 1568
#define WINSTRIDE (NHEAD * SLAB)      // 25088
#define PARTSTRIDE ((size_t)CDIM * MROWS)
#define KDIM 512
#define KITER (KDIM / 16)             // 32 iters of K=16
#define LP 52                          // padded token dim

// Scratch (device globals — no allocation)
__device__ float  g_qkvT[(size_t)NQKV * MROWS];     // qkv channel-major fp32
__device__ __half g_xhi[(size_t)MROWS * CDIM];      // x split hi/lo
__device__ __half g_xlo[(size_t)MROWS * CDIM];
__device__ __half g_ohi[(size_t)MROWS * CDIM];      // attn out, fp16 (hi only)
__device__ __half g_whi1[(size_t)NQKV * KDIM];      // w_qkv^T hi/lo [N][K]
__device__ __half g_wlo1[(size_t)NQKV * KDIM];
__device__ __half g_whi2[(size_t)CDIM * KDIM];      // w_proj^T hi/lo
__device__ __half g_wlo2[(size_t)CDIM * KDIM];

// ---------------------------------------------------------------------------
// PTX helpers (sm_80-era ISA — tcgen05 unavailable at compute_103)
// ---------------------------------------------------------------------------
__device__ __forceinline__ uint32_t smem_u32(const void* p) {
    uint32_t a;
    asm("{ .reg .u64 t; cvta.to.shared.u64 t, %1; cvt.u32.u64 %0, t; }"
        : "=r"(a) : "l"(p));
    return a;
}
__device__ __forceinline__ void cp_async16(uint32_t smem, const void* g) {
    asm volatile("cp.async.cg.shared.global [%0], [%1], 16;"
                 :: "r"(smem), "l"(g) : "memory");
}
__device__ __forceinline__ void cp_commit() {
    asm volatile("cp.async.commit_group;" ::: "memory");
}
template <int N>
__device__ __forceinline__ void cp_wait() {
    asm volatile("cp.async.wait_group %0;" :: "n"(N) : "memory");
}
__device__ __forceinline__ void ldsm_x4(uint32_t& r0, uint32_t& r1,
                                        uint32_t& r2, uint32_t& r3,
                                        uint32_t addr) {
    asm volatile("ldmatrix.sync.aligned.m8n8.x4.shared.b16 {%0,%1,%2,%3}, [%4];"
                 : "=r"(r0), "=r"(r1), "=r"(r2), "=r"(r3) : "r"(addr));
}
__device__ __forceinline__ void mma_f16(float* d, const uint32_t* a,
                                        const uint32_t* b) {
    asm volatile(
        "mma.sync.aligned.m16n8k16.row.col.f32.f16.f16.f32 "
        "{%0,%1,%2,%3}, {%4,%5,%6,%7}, {%8,%9}, {%0,%1,%2,%3};"
        : "+f"(d[0]), "+f"(d[1]), "+f"(d[2]), "+f"(d[3])
        : "r"(a[0]), "r"(a[1]), "r"(a[2]), "r"(a[3]), "r"(b[0]), "r"(b[1]));
}

#define STAGE_BYTES 16384
#define NSTAGE 4
#define DYN_SMEM 66560   // max(4*16384, 8 warps * 32*65*4 bounce)

__device__ __forceinline__ uint32_t sw16(int row, int c) {
    return (uint32_t)row * 32u + (uint32_t)((c ^ ((row >> 2) & 1)) << 4);
}

// ---------------------------------------------------------------------------
// x -> hi/lo fp16 split (elementwise)
// ---------------------------------------------------------------------------
__global__ __launch_bounds__(256) void split_x_kernel(const float* __restrict__ src) {
    size_t i = ((size_t)blockIdx.x * 256 + threadIdx.x) * 4;
    float4 v = *(const float4*)(src + i);
    __half h0 = __float2half_rn(v.x), h1 = __float2half_rn(v.y);
    __half h2 = __float2half_rn(v.z), h3 = __float2half_rn(v.w);
    __half l0 = __float2half_rn(v.x - __half2float(h0));
    __half l1 = __float2half_rn(v.y - __half2float(h1));
    __half l2 = __float2half_rn(v.z - __half2float(h2));
    __half l3 = __float2half_rn(v.w - __half2float(h3));
    __half2 hh[2] = {__halves2half2(h0, h1), __halves2half2(h2, h3)};
    __half2 ll[2] = {__halves2half2(l0, l1), __halves2half2(l2, l3)};
    *(uint2*)(g_xhi + i) = *(uint2*)hh;
    *(uint2*)(g_xlo + i) = *(uint2*)ll;
}

// ---------------------------------------------------------------------------
// Weight transpose + split: src[k*N + n] -> dst_{hi,lo}[n*K + k]
// ---------------------------------------------------------------------------
template <int SEL>
__global__ void wtrans_kernel(const float* __restrict__ src, int K, int N) {
    __half* dhi = (SEL == 1) ? g_whi1 : g_whi2;
    __half* dlo = (SEL == 1) ? g_wlo1 : g_wlo2;
    __shared__ float t[32][33];
    int n0 = blockIdx.x * 32, k0 = blockIdx.y * 32;
    int x = threadIdx.x, y = threadIdx.y;
    #pragma unroll
    for (int i = y; i < 32; i += 8)
        t[i][x] = src[(size_t)(k0 + i) * N + n0 + x];
    __syncthreads();
    #pragma unroll
    for (int i = y; i < 32; i += 8) {
        float v = t[x][i];
        __half h = __float2half_rn(v);
        __half l = __float2half_rn(v - __half2float(h));
        dhi[(size_t)(n0 + i) * K + k0 + x] = h;
        dlo[(size_t)(n0 + i) * K + k0 + x] = l;
    }
}

// ---------------------------------------------------------------------------
// fp16 split GEMM, variable term count (R5 shape: 256 thr, 2x4 warps, 64x32).
// TERMS=3: ah*bh + ah*bl + al*bh  (QK columns — softmax-amplified path)
// TERMS=2: ah*bh + ah*bl          (proj — A has no lo plane)
// TERMS=1: ah*bh                  (V columns — unamplified path)
// MODE 1: scatter epilogue g_qkvT[col*MROWS+row] (col offset bnOff*128)
// MODE 2: row-major epilogue to C
// ---------------------------------------------------------------------------
template <int MODE, int TERMS>
__global__ __launch_bounds__(256) void gemm_f16x3(
    const float* __restrict__ bias, float* __restrict__ C, int N, int bnOff)
{
    extern __shared__ char smem[];
    const __half* Ahi = (MODE == 1) ? g_xhi : g_ohi;
    const __half* Alo = (MODE == 1) ? g_xlo : g_ohi;   // dummy when TERMS<3
    const __half* Bhi = (MODE == 1) ? g_whi1 : g_whi2;
    const __half* Blo = (MODE == 1) ? g_wlo1 : g_wlo2;

    const int tid = threadIdx.x;
    const int lane = tid & 31, wid = tid >> 5;
    const int warpM = wid & 1, warpN = wid >> 1;   // 2 x 4 warps, 64x32 tiles
    const int bm = blockIdx.y, bn = blockIdx.x + bnOff;
    const uint32_t sbase = smem_u32(smem);

    // loader: 256 threads, per plane 256 chunks (128 rows x 2), one per thread
    const int grow = tid >> 1, gch = tid & 1;
    const uint32_t soff = sw16(grow, gch);
    const __half* gAhi = Ahi + (size_t)(bm * 128 + grow) * KDIM + gch * 8;
    const __half* gAlo = Alo + (size_t)(bm * 128 + grow) * KDIM + gch * 8;
    const __half* gBhi = Bhi + (size_t)(bn * 128 + grow) * KDIM + gch * 8;
    const __half* gBlo = Blo + (size_t)(bn * 128 + grow) * KDIM + gch * 8;

    float acc[4][4][4];
    #pragma unroll
    for (int i = 0; i < 4; i++)
        #pragma unroll
        for (int j = 0; j < 4; j++)
            #pragma unroll
            for (int q = 0; q < 4; q++) acc[i][j][q] = 0.f;

    #pragma unroll
    for (int s = 0; s < NSTAGE - 1; s++) {
        uint32_t st = sbase + s * STAGE_BYTES;
        int k0 = s * 16;
        cp_async16(st + soff, gAhi + k0);
        if (TERMS >= 3) cp_async16(st + 4096 + soff, gAlo + k0);
        cp_async16(st + 8192 + soff, gBhi + k0);
        if (TERMS >= 2) cp_async16(st + 12288 + soff, gBlo + k0);
        cp_commit();
    }

    const int lrow = lane & 15, lhalf = lane >> 4;
    uint32_t offA[4], offB[2];
    #pragma unroll
    for (int mt = 0; mt < 4; mt++)
        offA[mt] = sw16(warpM * 64 + mt * 16 + lrow, lhalf);
    #pragma unroll
    for (int nt2 = 0; nt2 < 2; nt2++)
        offB[nt2] = sw16(warpN * 32 + nt2 * 16 + lrow, lhalf);

    for (int it = 0; it < KITER; it++) {
        cp_wait<NSTAGE - 2>();
        __syncthreads();

        if (it + NSTAGE - 1 < KITER) {
            int s = (it + NSTAGE - 1) % NSTAGE;
            uint32_t st = sbase + s * STAGE_BYTES;
            int k0 = (it + NSTAGE - 1) * 16;
            cp_async16(st + soff, gAhi + k0);
            if (TERMS >= 3) cp_async16(st + 4096 + soff, gAlo + k0);
            cp_async16(st + 8192 + soff, gBhi + k0);
            if (TERMS >= 2) cp_async16(st + 12288 + soff, gBlo + k0);
        }
        cp_commit();

        const uint32_t st = sbase + (it % NSTAGE) * STAGE_BYTES;

        uint32_t ah[4][4], al[4][4], bh[4][2], bl[4][2];
        #pragma unroll
        for (int mt = 0; mt < 4; mt++) {
            ldsm_x4(ah[mt][0], ah[mt][1], ah[mt][2], ah[mt][3], st + offA[mt]);
            if (TERMS >= 3)
                ldsm_x4(al[mt][0], al[mt][1], al[mt][2], al[mt][3],
                        st + 4096 + offA[mt]);
        }
        #pragma unroll
        for (int nt2 = 0; nt2 < 2; nt2++) {
            uint32_t r0, r1, r2, r3;
            ldsm_x4(r0, r1, r2, r3, st + 8192 + offB[nt2]);
            bh[nt2 * 2 + 0][0] = r0; bh[nt2 * 2 + 0][1] = r2;
            bh[nt2 * 2 + 1][0] = r1; bh[nt2 * 2 + 1][1] = r3;
            if (TERMS >= 2) {
                ldsm_x4(r0, r1, r2, r3, st + 12288 + offB[nt2]);
                bl[nt2 * 2 + 0][0] = r0; bl[nt2 * 2 + 0][1] = r2;
                bl[nt2 * 2 + 1][0] = r1; bl[nt2 * 2 + 1][1] = r3;
            }
        }
        #pragma unroll
        for (int mt = 0; mt < 4; mt++)
            #pragma unroll
            for (int nt = 0; nt < 4; nt++) {
                mma_f16(acc[mt][nt], ah[mt], bh[nt]);
                if (TERMS >= 2) mma_f16(acc[mt][nt], ah[mt], bl[nt]);
                if (TERMS >= 3) mma_f16(acc[mt][nt], al[mt], bh[nt]);
            }
    }

    cp_wait<0>();
    __syncthreads();   // before smem reuse as bounce

    if (MODE == 2) {
        #pragma unroll
        for (int mt = 0; mt < 4; mt++) {
            #pragma unroll
            for (int nt = 0; nt < 4; nt++) {
                int m0 = bm * 128 + warpM * 64 + mt * 16 + (lane >> 2);
                int n0 = bn * 128 + warpN * 32 + nt * 8 + (lane & 3) * 2;
                float2 bv = *(const float2*)(bias + n0);
                float2 v0 = make_float2(acc[mt][nt][0] + bv.x, acc[mt][nt][1] + bv.y);
                float2 v1 = make_float2(acc[mt][nt][2] + bv.x, acc[mt][nt][3] + bv.y);
                *(float2*)(C + (size_t)m0 * N + n0) = v0;
                *(float2*)(C + (size_t)(m0 + 8) * N + n0) = v1;
            }
        }
    } else {
        float* bounce = (float*)smem + wid * (32 * 65);
        #pragma unroll
        for (int mt = 0; mt < 4; mt++) {
            #pragma unroll
            for (int nt = 0; nt < 4; nt++) {
                int nl = nt * 8 + (lane & 3) * 2;
                int ml = mt * 16 + (lane >> 2);
                bounce[nl * 65 + ml]            = acc[mt][nt][0];
                bounce[(nl + 1) * 65 + ml]      = acc[mt][nt][1];
                bounce[nl * 65 + ml + 8]        = acc[mt][nt][2];
                bounce[(nl + 1) * 65 + ml + 8]  = acc[mt][nt][3];
            }
        }
        __syncwarp();
        int col = bn * 128 + warpN * 32 + lane;
        float bv = bias[col];
        float* dst = g_qkvT + (size_t)col * MROWS + bm * 128 + warpM * 64;
        const float* src = bounce + lane * 65;
        #pragma unroll
        for (int q = 0; q < 16; q++) {
            float4 v;
            v.x = src[q * 4 + 0] + bv;
            v.y = src[q * 4 + 1] + bv;
            v.z = src[q * 4 + 2] + bv;
            v.w = src[q * 4 + 3] + bv;
            ((float4*)dst)[q] = v;
        }
    }
}

// ---------------------------------------------------------------------------
// Attention (register-tiled; fp16 hi-only output)
// ---------------------------------------------------------------------------
__global__ __launch_bounds__(256) void attn_kernel(
    const float* __restrict__ mask,
    const float* __restrict__ bias_table,
    const int*   __restrict__ index_table)
{
    __shared__ float sQT[HD * LP];
    __shared__ float sKT[HD * LP];
    __shared__ float sV[LTOK * HD];
    __shared__ float sS[LP * LP];

    int tid = threadIdx.x;
    int b2 = blockIdx.x >> 4;
    int h  = blockIdx.x & 15;

    size_t base = (size_t)b2 * WINSTRIDE + (size_t)h * SLAB;
    const float* Qg = g_qkvT + base;
    const float* Kg = g_qkvT + PARTSTRIDE + base;
    const float* Vg = g_qkvT + 2 * PARTSTRIDE + base;

    for (int t = tid; t < SLAB / 4; t += 256) {
        float4 qv = ((const float4*)Qg)[t];
        float4 kv = ((const float4*)Kg)[t];
        ((float4*)sV)[t] = ((const float4*)Vg)[t];
        int j  = t * 4;
        int l2 = j >> 5;
        int d  = j & 31;
        sQT[(d + 0) * LP + l2] = qv.x;
        sQT[(d + 1) * LP + l2] = qv.y;
        sQT[(d + 2) * LP + l2] = qv.z;
        sQT[(d + 3) * LP + l2] = qv.w;
        sKT[(d + 0) * LP + l2] = kv.x;
        sKT[(d + 1) * LP + l2] = kv.y;
        sKT[(d + 2) * LP + l2] = kv.z;
        sKT[(d + 3) * LP + l2] = kv.w;
    }
    __syncthreads();

    const float* mrow = mask + (size_t)(b2 & 63) * (LTOK * LTOK);
    if (tid < 169) {
        int lt = tid / 13, mt = tid - lt * 13;
        int l0 = lt * 4, m0 = mt * 4;
        float acc[4][4];
        #pragma unroll
        for (int i = 0; i < 4; i++)
            #pragma unroll
            for (int j = 0; j < 4; j++) acc[i][j] = 0.f;
        #pragma unroll
        for (int d = 0; d < HD; d++) {
            float4 q = *(const float4*)&sQT[d * LP + l0];
            float4 k = *(const float4*)&sKT[d * LP + m0];
            float qa[4] = {q.x, q.y, q.z, q.w};
            float ka[4] = {k.x, k.y, k.z, k.w};
            #pragma unroll
            for (int i = 0; i < 4; i++)
                #pragma unroll
                for (int j = 0; j < 4; j++)
                    acc[i][j] = fmaf(qa[i], ka[j], acc[i][j]);
        }
        #pragma unroll
        for (int i = 0; i < 4; i++) {
            int l = l0 + i;
            if (l < LTOK) {
                #pragma unroll
                for (int j = 0; j < 4; j++) {
                    int m = m0 + j;
                    if (m < LTOK) {
                        int o = l * LTOK + m;
                        sS[l * LP + m] = acc[i][j]
                            + bias_table[index_table[o] * NHEAD + h] + mrow[o];
                    }
                }
            }
        }
    }
    __syncthreads();

    int warp = tid >> 5, lane = tid & 31;
    for (int row = warp; row < LTOK; row += 8) {
        float* s = sS + row * LP;
        float e0 = s[lane];
        float e1 = (lane + 32 < LTOK) ? s[lane + 32] : -CUDART_INF_F;
        float mx = fmaxf(e0, e1);
        #pragma unroll
        for (int off = 16; off; off >>= 1)
            mx = fmaxf(mx, __shfl_xor_sync(0xffffffffu, mx, off));
        float p0 = __expf(e0 - mx);
        float p1 = (lane + 32 < LTOK) ? __expf(e1 - mx) : 0.f;
        float sum = p0 + p1;
        #pragma unroll
        for (int off = 16; off; off >>= 1)
            sum += __shfl_xor_sync(0xffffffffu, sum, off);
        float inv = 1.f / sum;
        s[lane] = p0 * inv;
        if (lane + 32 < LTOK) s[lane + 32] = p1 * inv;
    }
    __syncthreads();

    if (tid < 104) {
        int dt = tid & 7, lt = tid >> 3;
        int l0 = lt * 4, d0 = dt * 4;
        float acc[4][4];
        #pragma unroll
        for (int i = 0; i < 4; i++)
            #pragma unroll
            for (int j = 0; j < 4; j++) acc[i][j] = 0.f;
        for (int m = 0; m < LTOK; m++) {
            float4 v = *(const float4*)&sV[m * HD + d0];
            float va[4] = {v.x, v.y, v.z, v.w};
            float p0 = sS[(l0 + 0) * LP + m];
            float p1 = sS[(l0 + 1) * LP + m];
            float p2 = sS[(l0 + 2) * LP + m];
            float p3 = sS[(l0 + 3) * LP + m];
            #pragma unroll
            for (int j = 0; j < 4; j++) {
                acc[0][j] = fmaf(p0, va[j], acc[0][j]);
                acc[1][j] = fmaf(p1, va[j], acc[1][j]);
                acc[2][j] = fmaf(p2, va[j], acc[2][j]);
                acc[3][j] = fmaf(p3, va[j], acc[3][j]);
            }
        }
        #pragma unroll
        for (int i = 0; i < 4; i++) {
            int l = l0 + i;
            if (l < LTOK) {
                size_t oidx = ((size_t)b2 * LTOK + l) * CDIM + h * HD + d0;
                __half hv[4];
                #pragma unroll
                for (int j = 0; j < 4; j++)
                    hv[j] = __float2half_rn(acc[i][j]);
                *(uint2*)(g_ohi + oidx) = *(uint2*)hv;
            }
        }
    }
}

// ---------------------------------------------------------------------------
extern "C" void kernel_launch(void* const* d_in, const int* in_sizes, int n_in,
                              void* d_out, int out_size)
{
    const float* x           = (const float*)d_in[0];
    const float* mask        = (const float*)d_in[1];
    const float* w_qkv       = (const float*)d_in[2];
    const float* b_qkv       = (const float*)d_in[3];
    const float* w_proj      = (const float*)d_in[4];
    const float* b_proj      = (const float*)d_in[5];
    const float* bias_table  = (const float*)d_in[6];
    const int*   index_table = (const int*)d_in[7];
    float* out = (float*)d_out;

    cudaFuncSetAttribute(gemm_f16x3<1, 3>, cudaFuncAttributeMaxDynamicSharedMemorySize, DYN_SMEM);
    cudaFuncSetAttribute(gemm_f16x3<1, 1>, cudaFuncAttributeMaxDynamicSharedMemorySize, DYN_SMEM);
    cudaFuncSetAttribute(gemm_f16x3<2, 2>, cudaFuncAttributeMaxDynamicSharedMemorySize, DYN_SMEM);

    // 0) weight transpose+split and x split
    wtrans_kernel<1><<<dim3(NQKV / 32, KDIM / 32), dim3(32, 8)>>>(w_qkv, KDIM, NQKV);
    wtrans_kernel<2><<<dim3(CDIM / 32, KDIM / 32), dim3(32, 8)>>>(w_proj, KDIM, CDIM);
    split_x_kernel<<<((size_t)MROWS * CDIM) / 4 / 256, 256>>>(x);

    // 1a) QK columns (0..1023): 3-term — softmax-amplified precision path
    gemm_f16x3<1, 3><<<dim3(8, MROWS / 128), 256, DYN_SMEM>>>(b_qkv, nullptr, NQKV, 0);
    // 1b) V columns (1024..1535): 1-term — unamplified
    gemm_f16x3<1, 1><<<dim3(4, MROWS / 128), 256, DYN_SMEM>>>(b_qkv, nullptr, NQKV, 8);

    // 2) fused window attention (register-tiled)
    attn_kernel<<<BNW * NHEAD, 256>>>(mask, bias_table, index_table);

    // 3) projection GEMM: 2-term
    gemm_f16x3<2, 2><<<dim3(4, MROWS / 128), 256, DYN_SMEM>>>(b_proj, out, CDIM, 0);
}

// round 9
// speedup vs baseline: 1.3648x; 1.1184x over previous
#include <cuda_runtime.h>
#include <cuda_fp16.h>
#include <cstdint>
#include <math_constants.h>

// Problem constants
#define CDIM 512
#define NHEAD 16
#define HD 32
#define LTOK 49
#define BNW 4096
#define MROWS (BNW * LTOK)            // 200704
#define NQKV (3 * CDIM)               // 1536
#define SLAB (LTOK * HD)              // 1568
#define WINSTRIDE (NHEAD * SLAB)      // 25088
#define PARTSTRIDE ((size_t)CDIM * MROWS)
#define KDIM 512
#define KITER (KDIM / 16)             // 32 iters of K=16
#define LP 52                          // padded token dim
#define LL (LTOK * LTOK)               // 2401

// Scratch (device globals — no allocation)
__device__ float  g_qkvT[(size_t)NQKV * MROWS];     // qkv channel-major fp32
__device__ __half g_xhi[(size_t)MROWS * CDIM];      // x split hi/lo
__device__ __half g_xlo[(size_t)MROWS * CDIM];
__device__ __half g_ohi[(size_t)MROWS * CDIM];      // attn out, fp16 (hi only)
__device__ __half g_whi1[(size_t)NQKV * KDIM];      // w_qkv^T hi/lo [N][K]
__device__ __half g_wlo1[(size_t)NQKV * KDIM];
__device__ __half g_whi2[(size_t)CDIM * KDIM];      // w_proj^T hi (1-term)
__device__ __half g_wlo2[(size_t)CDIM * KDIM];
__device__ float  g_bm[64 * NHEAD * LL];            // fused bias+mask, 9.8MB

// ---------------------------------------------------------------------------
// PTX helpers (sm_80-era ISA — tcgen05 unavailable at compute_103)
// ---------------------------------------------------------------------------
__device__ __forceinline__ uint32_t smem_u32(const void* p) {
    uint32_t a;
    asm("{ .reg .u64 t; cvta.to.shared.u64 t, %1; cvt.u32.u64 %0, t; }"
        : "=r"(a) : "l"(p));
    return a;
}
__device__ __forceinline__ void cp_async16(uint32_t smem, const void* g) {
    asm volatile("cp.async.cg.shared.global [%0], [%1], 16;"
                 :: "r"(smem), "l"(g) : "memory");
}
__device__ __forceinline__ void cp_commit() {
    asm volatile("cp.async.commit_group;" ::: "memory");
}
template <int N>
__device__ __forceinline__ void cp_wait() {
    asm volatile("cp.async.wait_group %0;" :: "n"(N) : "memory");
}
__device__ __forceinline__ void ldsm_x4(uint32_t& r0, uint32_t& r1,
                                        uint32_t& r2, uint32_t& r3,
                                        uint32_t addr) {
    asm volatile("ldmatrix.sync.aligned.m8n8.x4.shared.b16 {%0,%1,%2,%3}, [%4];"
                 : "=r"(r0), "=r"(r1), "=r"(r2), "=r"(r3) : "r"(addr));
}
__device__ __forceinline__ void mma_f16(float* d, const uint32_t* a,
                                        const uint32_t* b) {
    asm volatile(
        "mma.sync.aligned.m16n8k16.row.col.f32.f16.f16.f32 "
        "{%0,%1,%2,%3}, {%4,%5,%6,%7}, {%8,%9}, {%0,%1,%2,%3};"
        : "+f"(d[0]), "+f"(d[1]), "+f"(d[2]), "+f"(d[3])
        : "r"(a[0]), "r"(a[1]), "r"(a[2]), "r"(a[3]), "r"(b[0]), "r"(b[1]));
}

#define STAGE_BYTES 16384
#define NSTAGE 4
#define DYN_SMEM 66560   // max(4*16384, 8 warps * 32*65*4 bounce)

__device__ __forceinline__ uint32_t sw16(int row, int c) {
    return (uint32_t)row * 32u + (uint32_t)((c ^ ((row >> 2) & 1)) << 4);
}

// ---------------------------------------------------------------------------
// x -> hi/lo fp16 split (elementwise)
// ---------------------------------------------------------------------------
__global__ __launch_bounds__(256) void split_x_kernel(const float* __restrict__ src) {
    size_t i = ((size_t)blockIdx.x * 256 + threadIdx.x) * 4;
    float4 v = *(const float4*)(src + i);
    __half h0 = __float2half_rn(v.x), h1 = __float2half_rn(v.y);
    __half h2 = __float2half_rn(v.z), h3 = __float2half_rn(v.w);
    __half l0 = __float2half_rn(v.x - __half2float(h0));
    __half l1 = __float2half_rn(v.y - __half2float(h1));
    __half l2 = __float2half_rn(v.z - __half2float(h2));
    __half l3 = __float2half_rn(v.w - __half2float(h3));
    __half2 hh[2] = {__halves2half2(h0, h1), __halves2half2(h2, h3)};
    __half2 ll[2] = {__halves2half2(l0, l1), __halves2half2(l2, l3)};
    *(uint2*)(g_xhi + i) = *(uint2*)hh;
    *(uint2*)(g_xlo + i) = *(uint2*)ll;
}

// ---------------------------------------------------------------------------
// Weight transpose + split: src[k*N + n] -> dst_{hi,lo}[n*K + k]
// ---------------------------------------------------------------------------
template <int SEL>
__global__ void wtrans_kernel(const float* __restrict__ src, int K, int N) {
    __half* dhi = (SEL == 1) ? g_whi1 : g_whi2;
    __half* dlo = (SEL == 1) ? g_wlo1 : g_wlo2;
    __shared__ float t[32][33];
    int n0 = blockIdx.x * 32, k0 = blockIdx.y * 32;
    int x = threadIdx.x, y = threadIdx.y;
    #pragma unroll
    for (int i = y; i < 32; i += 8)
        t[i][x] = src[(size_t)(k0 + i) * N + n0 + x];
    __syncthreads();
    #pragma unroll
    for (int i = y; i < 32; i += 8) {
        float v = t[x][i];
        __half h = __float2half_rn(v);
        __half l = __float2half_rn(v - __half2float(h));
        dhi[(size_t)(n0 + i) * K + k0 + x] = h;
        dlo[(size_t)(n0 + i) * K + k0 + x] = l;
    }
}

// ---------------------------------------------------------------------------
// Fused bias+mask precompute: g_bm[(w*16+h)*2401+o] = bias[idx[o]][h]+mask[w][o]
// ---------------------------------------------------------------------------
__global__ __launch_bounds__(256) void biasmask_kernel(
    const float* __restrict__ mask,
    const float* __restrict__ bias_table,
    const int*   __restrict__ index_table)
{
    int wh = blockIdx.x;
    int w = wh >> 4, h = wh & 15;
    const float* mrow = mask + (size_t)w * LL;
    float* dst = g_bm + (size_t)wh * LL;
    for (int o = threadIdx.x; o < LL; o += 256)
        dst[o] = bias_table[index_table[o] * NHEAD + h] + mrow[o];
}

// ---------------------------------------------------------------------------
// fp16 split GEMM, variable term count (256 thr, 2x4 warps, 64x32 warp tile).
// TERMS=3: ah*bh + ah*bl + al*bh  (QK columns — softmax-amplified path)
// TERMS=2: ah*bh + ah*bl
// TERMS=1: ah*bh                  (V columns, proj — unamplified paths)
// MODE 1: scatter epilogue g_qkvT[col*MROWS+row] (col offset bnOff*128)
// MODE 2: row-major epilogue to C
// ---------------------------------------------------------------------------
template <int MODE, int TERMS>
__global__ __launch_bounds__(256) void gemm_f16x3(
    const float* __restrict__ bias, float* __restrict__ C, int N, int bnOff)
{
    extern __shared__ char smem[];
    const __half* Ahi = (MODE == 1) ? g_xhi : g_ohi;
    const __half* Alo = (MODE == 1) ? g_xlo : g_ohi;   // dummy when TERMS<3
    const __half* Bhi = (MODE == 1) ? g_whi1 : g_whi2;
    const __half* Blo = (MODE == 1) ? g_wlo1 : g_wlo2;

    const int tid = threadIdx.x;
    const int lane = tid & 31, wid = tid >> 5;
    const int warpM = wid & 1, warpN = wid >> 1;   // 2 x 4 warps, 64x32 tiles
    const int bm = blockIdx.y, bn = blockIdx.x + bnOff;
    const uint32_t sbase = smem_u32(smem);

    const int grow = tid >> 1, gch = tid & 1;
    const uint32_t soff = sw16(grow, gch);
    const __half* gAhi = Ahi + (size_t)(bm * 128 + grow) * KDIM + gch * 8;
    const __half* gAlo = Alo + (size_t)(bm * 128 + grow) * KDIM + gch * 8;
    const __half* gBhi = Bhi + (size_t)(bn * 128 + grow) * KDIM + gch * 8;
    const __half* gBlo = Blo + (size_t)(bn * 128 + grow) * KDIM + gch * 8;

    float acc[4][4][4];
    #pragma unroll
    for (int i = 0; i < 4; i++)
        #pragma unroll
        for (int j = 0; j < 4; j++)
            #pragma unroll
            for (int q = 0; q < 4; q++) acc[i][j][q] = 0.f;

    #pragma unroll
    for (int s = 0; s < NSTAGE - 1; s++) {
        uint32_t st = sbase + s * STAGE_BYTES;
        int k0 = s * 16;
        cp_async16(st + soff, gAhi + k0);
        if (TERMS >= 3) cp_async16(st + 4096 + soff, gAlo + k0);
        cp_async16(st + 8192 + soff, gBhi + k0);
        if (TERMS >= 2) cp_async16(st + 12288 + soff, gBlo + k0);
        cp_commit();
    }

    const int lrow = lane & 15, lhalf = lane >> 4;
    uint32_t offA[4], offB[2];
    #pragma unroll
    for (int mt = 0; mt < 4; mt++)
        offA[mt] = sw16(warpM * 64 + mt * 16 + lrow, lhalf);
    #pragma unroll
    for (int nt2 = 0; nt2 < 2; nt2++)
        offB[nt2] = sw16(warpN * 32 + nt2 * 16 + lrow, lhalf);

    for (int it = 0; it < KITER; it++) {
        cp_wait<NSTAGE - 2>();
        __syncthreads();

        if (it + NSTAGE - 1 < KITER) {
            int s = (it + NSTAGE - 1) % NSTAGE;
            uint32_t st = sbase + s * STAGE_BYTES;
            int k0 = (it + NSTAGE - 1) * 16;
            cp_async16(st + soff, gAhi + k0);
            if (TERMS >= 3) cp_async16(st + 4096 + soff, gAlo + k0);
            cp_async16(st + 8192 + soff, gBhi + k0);
            if (TERMS >= 2) cp_async16(st + 12288 + soff, gBlo + k0);
        }
        cp_commit();

        const uint32_t st = sbase + (it % NSTAGE) * STAGE_BYTES;

        uint32_t ah[4][4], al[4][4], bh[4][2], bl[4][2];
        #pragma unroll
        for (int mt = 0; mt < 4; mt++) {
            ldsm_x4(ah[mt][0], ah[mt][1], ah[mt][2], ah[mt][3], st + offA[mt]);
            if (TERMS >= 3)
                ldsm_x4(al[mt][0], al[mt][1], al[mt][2], al[mt][3],
                        st + 4096 + offA[mt]);
        }
        #pragma unroll
        for (int nt2 = 0; nt2 < 2; nt2++) {
            uint32_t r0, r1, r2, r3;
            ldsm_x4(r0, r1, r2, r3, st + 8192 + offB[nt2]);
            bh[nt2 * 2 + 0][0] = r0; bh[nt2 * 2 + 0][1] = r2;
            bh[nt2 * 2 + 1][0] = r1; bh[nt2 * 2 + 1][1] = r3;
            if (TERMS >= 2) {
                ldsm_x4(r0, r1, r2, r3, st + 12288 + offB[nt2]);
                bl[nt2 * 2 + 0][0] = r0; bl[nt2 * 2 + 0][1] = r2;
                bl[nt2 * 2 + 1][0] = r1; bl[nt2 * 2 + 1][1] = r3;
            }
        }
        #pragma unroll
        for (int mt = 0; mt < 4; mt++)
            #pragma unroll
            for (int nt = 0; nt < 4; nt++) {
                mma_f16(acc[mt][nt], ah[mt], bh[nt]);
                if (TERMS >= 2) mma_f16(acc[mt][nt], ah[mt], bl[nt]);
                if (TERMS >= 3) mma_f16(acc[mt][nt], al[mt], bh[nt]);
            }
    }

    cp_wait<0>();
    __syncthreads();   // before smem reuse as bounce

    if (MODE == 2) {
        #pragma unroll
        for (int mt = 0; mt < 4; mt++) {
            #pragma unroll
            for (int nt = 0; nt < 4; nt++) {
                int m0 = bm * 128 + warpM * 64 + mt * 16 + (lane >> 2);
                int n0 = bn * 128 + warpN * 32 + nt * 8 + (lane & 3) * 2;
                float2 bv = *(const float2*)(bias + n0);
                float2 v0 = make_float2(acc[mt][nt][0] + bv.x, acc[mt][nt][1] + bv.y);
                float2 v1 = make_float2(acc[mt][nt][2] + bv.x, acc[mt][nt][3] + bv.y);
                *(float2*)(C + (size_t)m0 * N + n0) = v0;
                *(float2*)(C + (size_t)(m0 + 8) * N + n0) = v1;
            }
        }
    } else {
        float* bounce = (float*)smem + wid * (32 * 65);
        #pragma unroll
        for (int mt = 0; mt < 4; mt++) {
            #pragma unroll
            for (int nt = 0; nt < 4; nt++) {
                int nl = nt * 8 + (lane & 3) * 2;
                int ml = mt * 16 + (lane >> 2);
                bounce[nl * 65 + ml]            = acc[mt][nt][0];
                bounce[(nl + 1) * 65 + ml]      = acc[mt][nt][1];
                bounce[nl * 65 + ml + 8]        = acc[mt][nt][2];
                bounce[(nl + 1) * 65 + ml + 8]  = acc[mt][nt][3];
            }
        }
        __syncwarp();
        int col = bn * 128 + warpN * 32 + lane;
        float bv = bias[col];
        float* dst = g_qkvT + (size_t)col * MROWS + bm * 128 + warpM * 64;
        const float* src = bounce + lane * 65;
        #pragma unroll
        for (int q = 0; q < 16; q++) {
            float4 v;
            v.x = src[q * 4 + 0] + bv;
            v.y = src[q * 4 + 1] + bv;
            v.z = src[q * 4 + 2] + bv;
            v.w = src[q * 4 + 3] + bv;
            ((float4*)dst)[q] = v;
        }
    }
}

// ---------------------------------------------------------------------------
// Attention (register-tiled; fused bias+mask table; fp16 hi-only output)
// ---------------------------------------------------------------------------
__global__ __launch_bounds__(256) void attn_kernel()
{
    __shared__ float sQT[HD * LP];
    __shared__ float sKT[HD * LP];
    __shared__ float sV[LTOK * HD];
    __shared__ float sS[LP * LP];

    int tid = threadIdx.x;
    int b2 = blockIdx.x >> 4;
    int h  = blockIdx.x & 15;

    size_t base = (size_t)b2 * WINSTRIDE + (size_t)h * SLAB;
    const float* Qg = g_qkvT + base;
    const float* Kg = g_qkvT + PARTSTRIDE + base;
    const float* Vg = g_qkvT + 2 * PARTSTRIDE + base;
    const float* bm = g_bm + ((size_t)(b2 & 63) * NHEAD + h) * LL;

    for (int t = tid; t < SLAB / 4; t += 256) {
        float4 qv = ((const float4*)Qg)[t];
        float4 kv = ((const float4*)Kg)[t];
        ((float4*)sV)[t] = ((const float4*)Vg)[t];
        int j  = t * 4;
        int l2 = j >> 5;
        int d  = j & 31;
        sQT[(d + 0) * LP + l2] = qv.x;
        sQT[(d + 1) * LP + l2] = qv.y;
        sQT[(d + 2) * LP + l2] = qv.z;
        sQT[(d + 3) * LP + l2] = qv.w;
        sKT[(d + 0) * LP + l2] = kv.x;
        sKT[(d + 1) * LP + l2] = kv.y;
        sKT[(d + 2) * LP + l2] = kv.z;
        sKT[(d + 3) * LP + l2] = kv.w;
    }
    __syncthreads();

    if (tid < 169) {
        int lt = tid / 13, mt = tid - lt * 13;
        int l0 = lt * 4, m0 = mt * 4;
        float acc[4][4];
        #pragma unroll
        for (int i = 0; i < 4; i++)
            #pragma unroll
            for (int j = 0; j < 4; j++) acc[i][j] = 0.f;
        #pragma unroll
        for (int d = 0; d < HD; d++) {
            float4 q = *(const float4*)&sQT[d * LP + l0];
            float4 k = *(const float4*)&sKT[d * LP + m0];
            float qa[4] = {q.x, q.y, q.z, q.w};
            float ka[4] = {k.x, k.y, k.z, k.w};
            #pragma unroll
            for (int i = 0; i < 4; i++)
                #pragma unroll
                for (int j = 0; j < 4; j++)
                    acc[i][j] = fmaf(qa[i], ka[j], acc[i][j]);
        }
        #pragma unroll
        for (int i = 0; i < 4; i++) {
            int l = l0 + i;
            if (l < LTOK) {
                #pragma unroll
                for (int j = 0; j < 4; j++) {
                    int m = m0 + j;
                    if (m < LTOK)
                        sS[l * LP + m] = acc[i][j] + bm[l * LTOK + m];
                }
            }
        }
    }
    __syncthreads();

    int warp = tid >> 5, lane = tid & 31;
    for (int row = warp; row < LTOK; row += 8) {
        float* s = sS + row * LP;
        float e0 = s[lane];
        float e1 = (lane + 32 < LTOK) ? s[lane + 32] : -CUDART_INF_F;
        float mx = fmaxf(e0, e1);
        #pragma unroll
        for (int off = 16; off; off >>= 1)
            mx = fmaxf(mx, __shfl_xor_sync(0xffffffffu, mx, off));
        float p0 = __expf(e0 - mx);
        float p1 = (lane + 32 < LTOK) ? __expf(e1 - mx) : 0.f;
        float sum = p0 + p1;
        #pragma unroll
        for (int off = 16; off; off >>= 1)
            sum += __shfl_xor_sync(0xffffffffu, sum, off);
        float inv = 1.f / sum;
        s[lane] = p0 * inv;
        if (lane + 32 < LTOK) s[lane + 32] = p1 * inv;
    }
    __syncthreads();

    if (tid < 104) {
        int dt = tid & 7, lt = tid >> 3;
        int l0 = lt * 4, d0 = dt * 4;
        float acc[4][4];
        #pragma unroll
        for (int i = 0; i < 4; i++)
            #pragma unroll
            for (int j = 0; j < 4; j++) acc[i][j] = 0.f;
        for (int m = 0; m < LTOK; m++) {
            float4 v = *(const float4*)&sV[m * HD + d0];
            float va[4] = {v.x, v.y, v.z, v.w};
            float p0 = sS[(l0 + 0) * LP + m];
            float p1 = sS[(l0 + 1) * LP + m];
            float p2 = sS[(l0 + 2) * LP + m];
            float p3 = sS[(l0 + 3) * LP + m];
            #pragma unroll
            for (int j = 0; j < 4; j++) {
                acc[0][j] = fmaf(p0, va[j], acc[0][j]);
                acc[1][j] = fmaf(p1, va[j], acc[1][j]);
                acc[2][j] = fmaf(p2, va[j], acc[2][j]);
                acc[3][j] = fmaf(p3, va[j], acc[3][j]);
            }
        }
        #pragma unroll
        for (int i = 0; i < 4; i++) {
            int l = l0 + i;
            if (l < LTOK) {
                size_t oidx = ((size_t)b2 * LTOK + l) * CDIM + h * HD + d0;
                __half hv[4];
                #pragma unroll
                for (int j = 0; j < 4; j++)
                    hv[j] = __float2half_rn(acc[i][j]);
                *(uint2*)(g_ohi + oidx) = *(uint2*)hv;
            }
        }
    }
}

// ---------------------------------------------------------------------------
extern "C" void kernel_launch(void* const* d_in, const int* in_sizes, int n_in,
                              void* d_out, int out_size)
{
    const float* x           = (const float*)d_in[0];
    const float* mask        = (const float*)d_in[1];
    const float* w_qkv       = (const float*)d_in[2];
    const float* b_qkv       = (const float*)d_in[3];
    const float* w_proj      = (const float*)d_in[4];
    const float* b_proj      = (const float*)d_in[5];
    const float* bias_table  = (const float*)d_in[6];
    const int*   index_table = (const int*)d_in[7];
    float* out = (float*)d_out;

    cudaFuncSetAttribute(gemm_f16x3<1, 3>, cudaFuncAttributeMaxDynamicSharedMemorySize, DYN_SMEM);
    cudaFuncSetAttribute(gemm_f16x3<1, 1>, cudaFuncAttributeMaxDynamicSharedMemorySize, DYN_SMEM);
    cudaFuncSetAttribute(gemm_f16x3<2, 1>, cudaFuncAttributeMaxDynamicSharedMemorySize, DYN_SMEM);

    // 0) weight transpose+split, x split, fused bias+mask table
    wtrans_kernel<1><<<dim3(NQKV / 32, KDIM / 32), dim3(32, 8)>>>(w_qkv, KDIM, NQKV);
    wtrans_kernel<2><<<dim3(CDIM / 32, KDIM / 32), dim3(32, 8)>>>(w_proj, KDIM, CDIM);
    split_x_kernel<<<((size_t)MROWS * CDIM) / 4 / 256, 256>>>(x);
    biasmask_kernel<<<64 * NHEAD, 256>>>(mask, bias_table, index_table);

    // 1a) QK columns (0..1023): 3-term — softmax-amplified precision path
    gemm_f16x3<1, 3><<<dim3(8, MROWS / 128), 256, DYN_SMEM>>>(b_qkv, nullptr, NQKV, 0);
    // 1b) V columns (1024..1535): 1-term — unamplified
    gemm_f16x3<1, 1><<<dim3(4, MROWS / 128), 256, DYN_SMEM>>>(b_qkv, nullptr, NQKV, 8);

    // 2) fused window attention (register-tiled)
    attn_kernel<<<BNW * NHEAD, 256>>>();

    // 3) projection GEMM: 1-term (unamplified path)
    gemm_f16x3<2, 1><<<dim3(4, MROWS / 128), 256, DYN_SMEM>>>(b_proj, out, CDIM, 0);
}

// round 10
// speedup vs baseline: 1.4039x; 1.0286x over previous
#include <cuda_runtime.h>
#include <cuda_fp16.h>
#include <cstdint>
#include <math_constants.h>

// Problem constants
#define CDIM 512
#define NHEAD 16
#define HD 32
#define LTOK 49
#define BNW 4096
#define MROWS (BNW * LTOK)            // 200704
#define NQKV (3 * CDIM)               // 1536
#define SLAB (LTOK * HD)              // 1568
#define WINSTRIDE (NHEAD * SLAB)      // 25088
#define PARTSTRIDE ((size_t)CDIM * MROWS)
#define KDIM 512
#define KITER (KDIM / 16)             // 32 iters of K=16
#define LP 52                          // padded token dim
#define LL (LTOK * LTOK)               // 2401

// Scratch (device globals — no allocation)
__device__ float  g_qkvT[(size_t)1024 * MROWS];     // Q,K channel-major fp32
__device__ __half g_vh[(size_t)CDIM * MROWS];       // V channel-major fp16
__device__ __half g_xhi[(size_t)MROWS * CDIM];      // x split hi/lo
__device__ __half g_xlo[(size_t)MROWS * CDIM];
__device__ __half g_ohi[(size_t)MROWS * CDIM];      // attn out, fp16 (hi only)
__device__ __half g_whi1[(size_t)NQKV * KDIM];      // w_qkv^T hi/lo [N][K]
__device__ __half g_wlo1[(size_t)NQKV * KDIM];
__device__ __half g_whi2[(size_t)CDIM * KDIM];      // w_proj^T hi (1-term)
__device__ __half g_wlo2[(size_t)CDIM * KDIM];
__device__ __half g_bmh[64 * NHEAD * LL];           // fused bias+mask, fp16

// ---------------------------------------------------------------------------
// PTX helpers (sm_80-era ISA — tcgen05 unavailable at compute_103)
// ---------------------------------------------------------------------------
__device__ __forceinline__ uint32_t smem_u32(const void* p) {
    uint32_t a;
    asm("{ .reg .u64 t; cvta.to.shared.u64 t, %1; cvt.u32.u64 %0, t; }"
        : "=r"(a) : "l"(p));
    return a;
}
__device__ __forceinline__ void cp_async16(uint32_t smem, const void* g) {
    asm volatile("cp.async.cg.shared.global [%0], [%1], 16;"
                 :: "r"(smem), "l"(g) : "memory");
}
__device__ __forceinline__ void cp_commit() {
    asm volatile("cp.async.commit_group;" ::: "memory");
}
template <int N>
__device__ __forceinline__ void cp_wait() {
    asm volatile("cp.async.wait_group %0;" :: "n"(N) : "memory");
}
__device__ __forceinline__ void ldsm_x4(uint32_t& r0, uint32_t& r1,
                                        uint32_t& r2, uint32_t& r3,
                                        uint32_t addr) {
    asm volatile("ldmatrix.sync.aligned.m8n8.x4.shared.b16 {%0,%1,%2,%3}, [%4];"
                 : "=r"(r0), "=r"(r1), "=r"(r2), "=r"(r3) : "r"(addr));
}
__device__ __forceinline__ void mma_f16(float* d, const uint32_t* a,
                                        const uint32_t* b) {
    asm volatile(
        "mma.sync.aligned.m16n8k16.row.col.f32.f16.f16.f32 "
        "{%0,%1,%2,%3}, {%4,%5,%6,%7}, {%8,%9}, {%0,%1,%2,%3};"
        : "+f"(d[0]), "+f"(d[1]), "+f"(d[2]), "+f"(d[3])
        : "r"(a[0]), "r"(a[1]), "r"(a[2]), "r"(a[3]), "r"(b[0]), "r"(b[1]));
}

#define STAGE_BYTES 16384
#define NSTAGE 4
#define DYN_SMEM 66560   // max(4*16384, 8 warps * 32*65*4 bounce)

__device__ __forceinline__ uint32_t sw16(int row, int c) {
    return (uint32_t)row * 32u + (uint32_t)((c ^ ((row >> 2) & 1)) << 4);
}

// ---------------------------------------------------------------------------
// x -> hi/lo fp16 split (elementwise)
// ---------------------------------------------------------------------------
__global__ __launch_bounds__(256) void split_x_kernel(const float* __restrict__ src) {
    size_t i = ((size_t)blockIdx.x * 256 + threadIdx.x) * 4;
    float4 v = *(const float4*)(src + i);
    __half h0 = __float2half_rn(v.x), h1 = __float2half_rn(v.y);
    __half h2 = __float2half_rn(v.z), h3 = __float2half_rn(v.w);
    __half l0 = __float2half_rn(v.x - __half2float(h0));
    __half l1 = __float2half_rn(v.y - __half2float(h1));
    __half l2 = __float2half_rn(v.z - __half2float(h2));
    __half l3 = __float2half_rn(v.w - __half2float(h3));
    __half2 hh[2] = {__halves2half2(h0, h1), __halves2half2(h2, h3)};
    __half2 ll[2] = {__halves2half2(l0, l1), __halves2half2(l2, l3)};
    *(uint2*)(g_xhi + i) = *(uint2*)hh;
    *(uint2*)(g_xlo + i) = *(uint2*)ll;
}

// ---------------------------------------------------------------------------
// Weight transpose + split: src[k*N + n] -> dst_{hi,lo}[n*K + k]
// ---------------------------------------------------------------------------
template <int SEL>
__global__ void wtrans_kernel(const float* __restrict__ src, int K, int N) {
    __half* dhi = (SEL == 1) ? g_whi1 : g_whi2;
    __half* dlo = (SEL == 1) ? g_wlo1 : g_wlo2;
    __shared__ float t[32][33];
    int n0 = blockIdx.x * 32, k0 = blockIdx.y * 32;
    int x = threadIdx.x, y = threadIdx.y;
    #pragma unroll
    for (int i = y; i < 32; i += 8)
        t[i][x] = src[(size_t)(k0 + i) * N + n0 + x];
    __syncthreads();
    #pragma unroll
    for (int i = y; i < 32; i += 8) {
        float v = t[x][i];
        __half h = __float2half_rn(v);
        __half l = __float2half_rn(v - __half2float(h));
        dhi[(size_t)(n0 + i) * K + k0 + x] = h;
        dlo[(size_t)(n0 + i) * K + k0 + x] = l;
    }
}

// ---------------------------------------------------------------------------
// Fused bias+mask precompute (fp16 output)
// ---------------------------------------------------------------------------
__global__ __launch_bounds__(256) void biasmask_kernel(
    const float* __restrict__ mask,
    const float* __restrict__ bias_table,
    const int*   __restrict__ index_table)
{
    int wh = blockIdx.x;
    int w = wh >> 4, h = wh & 15;
    const float* mrow = mask + (size_t)w * LL;
    __half* dst = g_bmh + (size_t)wh * LL;
    for (int o = threadIdx.x; o < LL; o += 256)
        dst[o] = __float2half_rn(bias_table[index_table[o] * NHEAD + h] + mrow[o]);
}

// ---------------------------------------------------------------------------
// fp16 split GEMM, variable term count (256 thr, 2x4 warps, 64x32 warp tile).
// TERMS=3 MODE=1: QK columns -> fp32 scatter to g_qkvT
// TERMS=1 MODE=1: V columns  -> fp16 scatter to g_vh
// TERMS=1 MODE=2: proj       -> row-major fp32 to C
// ---------------------------------------------------------------------------
template <int MODE, int TERMS>
__global__ __launch_bounds__(256) void gemm_f16x3(
    const float* __restrict__ bias, float* __restrict__ C, int N, int bnOff)
{
    extern __shared__ char smem[];
    const __half* Ahi = (MODE == 1) ? g_xhi : g_ohi;
    const __half* Alo = (MODE == 1) ? g_xlo : g_ohi;   // dummy when TERMS<3
    const __half* Bhi = (MODE == 1) ? g_whi1 : g_whi2;
    const __half* Blo = (MODE == 1) ? g_wlo1 : g_wlo2;

    const int tid = threadIdx.x;
    const int lane = tid & 31, wid = tid >> 5;
    const int warpM = wid & 1, warpN = wid >> 1;   // 2 x 4 warps, 64x32 tiles
    const int bm = blockIdx.y, bn = blockIdx.x + bnOff;
    const uint32_t sbase = smem_u32(smem);

    const int grow = tid >> 1, gch = tid & 1;
    const uint32_t soff = sw16(grow, gch);
    const __half* gAhi = Ahi + (size_t)(bm * 128 + grow) * KDIM + gch * 8;
    const __half* gAlo = Alo + (size_t)(bm * 128 + grow) * KDIM + gch * 8;
    const __half* gBhi = Bhi + (size_t)(bn * 128 + grow) * KDIM + gch * 8;
    const __half* gBlo = Blo + (size_t)(bn * 128 + grow) * KDIM + gch * 8;

    float acc[4][4][4];
    #pragma unroll
    for (int i = 0; i < 4; i++)
        #pragma unroll
        for (int j = 0; j < 4; j++)
            #pragma unroll
            for (int q = 0; q < 4; q++) acc[i][j][q] = 0.f;

    #pragma unroll
    for (int s = 0; s < NSTAGE - 1; s++) {
        uint32_t st = sbase + s * STAGE_BYTES;
        int k0 = s * 16;
        cp_async16(st + soff, gAhi + k0);
        if (TERMS >= 3) cp_async16(st + 4096 + soff, gAlo + k0);
        cp_async16(st + 8192 + soff, gBhi + k0);
        if (TERMS >= 2) cp_async16(st + 12288 + soff, gBlo + k0);
        cp_commit();
    }

    const int lrow = lane & 15, lhalf = lane >> 4;
    uint32_t offA[4], offB[2];
    #pragma unroll
    for (int mt = 0; mt < 4; mt++)
        offA[mt] = sw16(warpM * 64 + mt * 16 + lrow, lhalf);
    #pragma unroll
    for (int nt2 = 0; nt2 < 2; nt2++)
        offB[nt2] = sw16(warpN * 32 + nt2 * 16 + lrow, lhalf);

    for (int it = 0; it < KITER; it++) {
        cp_wait<NSTAGE - 2>();
        __syncthreads();

        if (it + NSTAGE - 1 < KITER) {
            int s = (it + NSTAGE - 1) % NSTAGE;
            uint32_t st = sbase + s * STAGE_BYTES;
            int k0 = (it + NSTAGE - 1) * 16;
            cp_async16(st + soff, gAhi + k0);
            if (TERMS >= 3) cp_async16(st + 4096 + soff, gAlo + k0);
            cp_async16(st + 8192 + soff, gBhi + k0);
            if (TERMS >= 2) cp_async16(st + 12288 + soff, gBlo + k0);
        }
        cp_commit();

        const uint32_t st = sbase + (it % NSTAGE) * STAGE_BYTES;

        uint32_t ah[4][4], al[4][4], bh[4][2], bl[4][2];
        #pragma unroll
        for (int mt = 0; mt < 4; mt++) {
            ldsm_x4(ah[mt][0], ah[mt][1], ah[mt][2], ah[mt][3], st + offA[mt]);
            if (TERMS >= 3)
                ldsm_x4(al[mt][0], al[mt][1], al[mt][2], al[mt][3],
                        st + 4096 + offA[mt]);
        }
        #pragma unroll
        for (int nt2 = 0; nt2 < 2; nt2++) {
            uint32_t r0, r1, r2, r3;
            ldsm_x4(r0, r1, r2, r3, st + 8192 + offB[nt2]);
            bh[nt2 * 2 + 0][0] = r0; bh[nt2 * 2 + 0][1] = r2;
            bh[nt2 * 2 + 1][0] = r1; bh[nt2 * 2 + 1][1] = r3;
            if (TERMS >= 2) {
                ldsm_x4(r0, r1, r2, r3, st + 12288 + offB[nt2]);
                bl[nt2 * 2 + 0][0] = r0; bl[nt2 * 2 + 0][1] = r2;
                bl[nt2 * 2 + 1][0] = r1; bl[nt2 * 2 + 1][1] = r3;
            }
        }
        #pragma unroll
        for (int mt = 0; mt < 4; mt++)
            #pragma unroll
            for (int nt = 0; nt < 4; nt++) {
                mma_f16(acc[mt][nt], ah[mt], bh[nt]);
                if (TERMS >= 2) mma_f16(acc[mt][nt], ah[mt], bl[nt]);
                if (TERMS >= 3) mma_f16(acc[mt][nt], al[mt], bh[nt]);
            }
    }

    cp_wait<0>();
    __syncthreads();   // before smem reuse as bounce

    if (MODE == 2) {
        #pragma unroll
        for (int mt = 0; mt < 4; mt++) {
            #pragma unroll
            for (int nt = 0; nt < 4; nt++) {
                int m0 = bm * 128 + warpM * 64 + mt * 16 + (lane >> 2);
                int n0 = bn * 128 + warpN * 32 + nt * 8 + (lane & 3) * 2;
                float2 bv = *(const float2*)(bias + n0);
                float2 v0 = make_float2(acc[mt][nt][0] + bv.x, acc[mt][nt][1] + bv.y);
                float2 v1 = make_float2(acc[mt][nt][2] + bv.x, acc[mt][nt][3] + bv.y);
                *(float2*)(C + (size_t)m0 * N + n0) = v0;
                *(float2*)(C + (size_t)(m0 + 8) * N + n0) = v1;
            }
        }
    } else {
        float* bounce = (float*)smem + wid * (32 * 65);
        #pragma unroll
        for (int mt = 0; mt < 4; mt++) {
            #pragma unroll
            for (int nt = 0; nt < 4; nt++) {
                int nl = nt * 8 + (lane & 3) * 2;
                int ml = mt * 16 + (lane >> 2);
                bounce[nl * 65 + ml]            = acc[mt][nt][0];
                bounce[(nl + 1) * 65 + ml]      = acc[mt][nt][1];
                bounce[nl * 65 + ml + 8]        = acc[mt][nt][2];
                bounce[(nl + 1) * 65 + ml + 8]  = acc[mt][nt][3];
            }
        }
        __syncwarp();
        int col = bn * 128 + warpN * 32 + lane;
        float bv = bias[col];
        const float* src = bounce + lane * 65;
        if (TERMS == 1) {
            // V columns: fp16 scatter to g_vh
            __half* dst = g_vh + (size_t)(col - 1024) * MROWS
                        + bm * 128 + warpM * 64;
            #pragma unroll
            for (int q = 0; q < 16; q++) {
                __half h[4];
                h[0] = __float2half_rn(src[q * 4 + 0] + bv);
                h[1] = __float2half_rn(src[q * 4 + 1] + bv);
                h[2] = __float2half_rn(src[q * 4 + 2] + bv);
                h[3] = __float2half_rn(src[q * 4 + 3] + bv);
                *(uint2*)(dst + q * 4) = *(uint2*)h;
            }
        } else {
            float* dst = g_qkvT + (size_t)col * MROWS + bm * 128 + warpM * 64;
            #pragma unroll
            for (int q = 0; q < 16; q++) {
                float4 v;
                v.x = src[q * 4 + 0] + bv;
                v.y = src[q * 4 + 1] + bv;
                v.z = src[q * 4 + 2] + bv;
                v.w = src[q * 4 + 3] + bv;
                ((float4*)dst)[q] = v;
            }
        }
    }
}

// ---------------------------------------------------------------------------
// Attention: fp32 Q,K slabs; fp16 V slab; fp16 bm table; PV re-tiled 4x2.
// ---------------------------------------------------------------------------
__global__ __launch_bounds__(256) void attn_kernel()
{
    __shared__ float  sQT[HD * LP];
    __shared__ float  sKT[HD * LP];
    __shared__ __half sVh[SLAB];          // [l][d] fp16
    __shared__ float  sS[LP * LP];

    int tid = threadIdx.x;
    int b2 = blockIdx.x >> 4;
    int h  = blockIdx.x & 15;

    size_t base = (size_t)b2 * WINSTRIDE + (size_t)h * SLAB;
    const float*  Qg  = g_qkvT + base;
    const float*  Kg  = g_qkvT + PARTSTRIDE + base;
    const __half* Vgh = g_vh + base;
    const __half* bm  = g_bmh + ((size_t)(b2 & 63) * NHEAD + h) * LL;

    // Load Q,K transposed to [d][l]; V fp16 straight copy (196 x uint4)
    if (tid < 196)
        ((uint4*)sVh)[tid] = ((const uint4*)Vgh)[tid];
    for (int t = tid; t < SLAB / 4; t += 256) {
        float4 qv = ((const float4*)Qg)[t];
        float4 kv = ((const float4*)Kg)[t];
        int j  = t * 4;
        int l2 = j >> 5;
        int d  = j & 31;
        sQT[(d + 0) * LP + l2] = qv.x;
        sQT[(d + 1) * LP + l2] = qv.y;
        sQT[(d + 2) * LP + l2] = qv.z;
        sQT[(d + 3) * LP + l2] = qv.w;
        sKT[(d + 0) * LP + l2] = kv.x;
        sKT[(d + 1) * LP + l2] = kv.y;
        sKT[(d + 2) * LP + l2] = kv.z;
        sKT[(d + 3) * LP + l2] = kv.w;
    }
    __syncthreads();

    // Scores: 13x13 grid of 4x4 tiles
    if (tid < 169) {
        int lt = tid / 13, mt = tid - lt * 13;
        int l0 = lt * 4, m0 = mt * 4;
        float acc[4][4];
        #pragma unroll
        for (int i = 0; i < 4; i++)
            #pragma unroll
            for (int j = 0; j < 4; j++) acc[i][j] = 0.f;
        #pragma unroll
        for (int d = 0; d < HD; d++) {
            float4 q = *(const float4*)&sQT[d * LP + l0];
            float4 k = *(const float4*)&sKT[d * LP + m0];
            float qa[4] = {q.x, q.y, q.z, q.w};
            float ka[4] = {k.x, k.y, k.z, k.w};
            #pragma unroll
            for (int i = 0; i < 4; i++)
                #pragma unroll
                for (int j = 0; j < 4; j++)
                    acc[i][j] = fmaf(qa[i], ka[j], acc[i][j]);
        }
        #pragma unroll
        for (int i = 0; i < 4; i++) {
            int l = l0 + i;
            if (l < LTOK) {
                #pragma unroll
                for (int j = 0; j < 4; j++) {
                    int m = m0 + j;
                    if (m < LTOK)
                        sS[l * LP + m] = acc[i][j]
                            + __half2float(bm[l * LTOK + m]);
                }
            }
        }
    }
    __syncthreads();

    // Softmax per row (warp per row)
    int warp = tid >> 5, lane = tid & 31;
    for (int row = warp; row < LTOK; row += 8) {
        float* s = sS + row * LP;
        float e0 = s[lane];
        float e1 = (lane + 32 < LTOK) ? s[lane + 32] : -CUDART_INF_F;
        float mx = fmaxf(e0, e1);
        #pragma unroll
        for (int off = 16; off; off >>= 1)
            mx = fmaxf(mx, __shfl_xor_sync(0xffffffffu, mx, off));
        float p0 = __expf(e0 - mx);
        float p1 = (lane + 32 < LTOK) ? __expf(e1 - mx) : 0.f;
        float sum = p0 + p1;
        #pragma unroll
        for (int off = 16; off; off >>= 1)
            sum += __shfl_xor_sync(0xffffffffu, sum, off);
        float inv = 1.f / sum;
        s[lane] = p0 * inv;
        if (lane + 32 < LTOK) s[lane + 32] = p1 * inv;
    }
    __syncthreads();

    // PV: 13(l) x 16(d) grid of 4x2 tiles (208 units, 81% util)
    if (tid < 208) {
        int dt = tid & 15, lt = tid >> 4;
        int l0 = lt * 4, d0 = dt * 2;
        const __half2* v2 = (const __half2*)sVh;
        float acc[4][2];
        #pragma unroll
        for (int i = 0; i < 4; i++) { acc[i][0] = 0.f; acc[i][1] = 0.f; }
        for (int m = 0; m < LTOK; m++) {
            float2 vf = __half22float2(v2[m * 16 + dt]);
            float p0 = sS[(l0 + 0) * LP + m];
            float p1 = sS[(l0 + 1) * LP + m];
            float p2 = sS[(l0 + 2) * LP + m];
            float p3 = sS[(l0 + 3) * LP + m];
            acc[0][0] = fmaf(p0, vf.x, acc[0][0]);
            acc[0][1] = fmaf(p0, vf.y, acc[0][1]);
            acc[1][0] = fmaf(p1, vf.x, acc[1][0]);
            acc[1][1] = fmaf(p1, vf.y, acc[1][1]);
            acc[2][0] = fmaf(p2, vf.x, acc[2][0]);
            acc[2][1] = fmaf(p2, vf.y, acc[2][1]);
            acc[3][0] = fmaf(p3, vf.x, acc[3][0]);
            acc[3][1] = fmaf(p3, vf.y, acc[3][1]);
        }
        #pragma unroll
        for (int i = 0; i < 4; i++) {
            int l = l0 + i;
            if (l < LTOK) {
                size_t oidx = ((size_t)b2 * LTOK + l) * CDIM + h * HD + d0;
                __half2 hv = __floats2half2_rn(acc[i][0], acc[i][1]);
                *(__half2*)(g_ohi + oidx) = hv;
            }
        }
    }
}

// ---------------------------------------------------------------------------
extern "C" void kernel_launch(void* const* d_in, const int* in_sizes, int n_in,
                              void* d_out, int out_size)
{
    const float* x           = (const float*)d_in[0];
    const float* mask        = (const float*)d_in[1];
    const float* w_qkv       = (const float*)d_in[2];
    const float* b_qkv       = (const float*)d_in[3];
    const float* w_proj      = (const float*)d_in[4];
    const float* b_proj      = (const float*)d_in[5];
    const float* bias_table  = (const float*)d_in[6];
    const int*   index_table = (const int*)d_in[7];
    float* out = (float*)d_out;

    cudaFuncSetAttribute(gemm_f16x3<1, 3>, cudaFuncAttributeMaxDynamicSharedMemorySize, DYN_SMEM);
    cudaFuncSetAttribute(gemm_f16x3<1, 1>, cudaFuncAttributeMaxDynamicSharedMemorySize, DYN_SMEM);
    cudaFuncSetAttribute(gemm_f16x3<2, 1>, cudaFuncAttributeMaxDynamicSharedMemorySize, DYN_SMEM);

    // 0) weight transpose+split, x split, fused bias+mask table (fp16)
    wtrans_kernel<1><<<dim3(NQKV / 32, KDIM / 32), dim3(32, 8)>>>(w_qkv, KDIM, NQKV);
    wtrans_kernel<2><<<dim3(CDIM / 32, KDIM / 32), dim3(32, 8)>>>(w_proj, KDIM, CDIM);
    split_x_kernel<<<((size_t)MROWS * CDIM) / 4 / 256, 256>>>(x);
    biasmask_kernel<<<64 * NHEAD, 256>>>(mask, bias_table, index_table);

    // 1a) QK columns (0..1023): 3-term fp32 scatter
    gemm_f16x3<1, 3><<<dim3(8, MROWS / 128), 256, DYN_SMEM>>>(b_qkv, nullptr, NQKV, 0);
    // 1b) V columns (1024..1535): 1-term fp16 scatter
    gemm_f16x3<1, 1><<<dim3(4, MROWS / 128), 256, DYN_SMEM>>>(b_qkv, nullptr, NQKV, 8);

    // 2) fused window attention
    attn_kernel<<<BNW * NHEAD, 256>>>();

    // 3) projection GEMM: 1-term
    gemm_f16x3<2, 1><<<dim3(4, MROWS / 128), 256, DYN_SMEM>>>(b_proj, out, CDIM, 0);
}